// round 13
// baseline (speedup 1.0000x reference)
#include <cuda_runtime.h>
#include <cuda_bf16.h>
#include <cuda_fp16.h>
#include <cstdint>

// Problem constants (fixed shapes from reference)
#define B_  8
#define C_  256
#define CK_ 64
#define N_  2304

typedef unsigned short u16;

// ---------------- scratch (__device__ globals) ------------------------------------
__device__ u16   g_xthi[B_ * N_ * C_];        // x transposed [b][n][c], bf16 hi
__device__ u16   g_xtlo[B_ * N_ * C_];        // lo plane
__device__ u16   g_Wqkhi[128 * C_];           // q(64)+k(64) weights [ck][c]
__device__ u16   g_Wqklo[128 * C_];
__device__ u16   g_Wgvhi[C_ * C_];            // (gamma@value) weights [c_out][c]
__device__ u16   g_Wgvlo[C_ * C_];
__device__ float g_biasA[384];                // qb|kb|gv bias
__device__ u16   g_QKthi[B_ * N_ * 128];      // Qt|Kt [b][i][ck] bf16 hi
__device__ u16   g_QKtlo[B_ * N_ * 128];
__device__ u16   g_Ef[(long)B_ * N_ * N_];    // exp(QK) [b][j][i], single fp16 plane
__device__ u16   g_Af[B_ * C_ * N_];          // (GV/D * 4096) single fp16 plane
__device__ float g_D[B_ * N_];                // row sums over j, then reciprocals

#define ASCALE 4096.0f

// ---------------- helpers ----------------------------------------------------------
__device__ __forceinline__ void mma_bf16(float* c,
    uint32_t a0, uint32_t a1, uint32_t a2, uint32_t a3, uint32_t b0, uint32_t b1)
{
    asm volatile(
        "mma.sync.aligned.m16n8k16.row.col.f32.bf16.bf16.f32 "
        "{%0,%1,%2,%3}, {%4,%5,%6,%7}, {%8,%9}, {%0,%1,%2,%3};"
        : "+f"(c[0]), "+f"(c[1]), "+f"(c[2]), "+f"(c[3])
        : "r"(a0), "r"(a1), "r"(a2), "r"(a3), "r"(b0), "r"(b1));
}
__device__ __forceinline__ void mma_f16(float* c,
    uint32_t a0, uint32_t a1, uint32_t a2, uint32_t a3, uint32_t b0, uint32_t b1)
{
    asm volatile(
        "mma.sync.aligned.m16n8k16.row.col.f32.f16.f16.f32 "
        "{%0,%1,%2,%3}, {%4,%5,%6,%7}, {%8,%9}, {%0,%1,%2,%3};"
        : "+f"(c[0]), "+f"(c[1]), "+f"(c[2]), "+f"(c[3])
        : "r"(a0), "r"(a1), "r"(a2), "r"(a3), "r"(b0), "r"(b1));
}
__device__ __forceinline__ void ldsm4(uint32_t* r, uint32_t addr)
{
    asm volatile("ldmatrix.sync.aligned.m8n8.x4.shared.b16 {%0,%1,%2,%3}, [%4];"
        : "=r"(r[0]), "=r"(r[1]), "=r"(r[2]), "=r"(r[3]) : "r"(addr));
}

// split (a,b) into packed bf16x2 hi + lo planes (low half = a)
__device__ __forceinline__ void split2(float a, float b, uint32_t& hi, uint32_t& lo)
{
    uint32_t h;
    asm("cvt.rn.bf16x2.f32 %0, %1, %2;" : "=r"(h) : "f"(b), "f"(a));
    float ha = __uint_as_float(h << 16);
    float hb = __uint_as_float(h & 0xffff0000u);
    float la = a - ha, lb = b - hb;
    uint32_t l;
    asm("cvt.rn.bf16x2.f32 %0, %1, %2;" : "=r"(l) : "f"(lb), "f"(la));
    hi = h; lo = l;
}

__device__ __forceinline__ uint32_t smem_u32(const void* p) {
    uint32_t a;
    asm("{ .reg .u64 t; cvta.to.shared.u64 t, %1; cvt.u32.u64 %0, t; }" : "=r"(a) : "l"(p));
    return a;
}
__device__ __forceinline__ void cp16(uint32_t dst, const void* src) {
    asm volatile("cp.async.cg.shared.global [%0], [%1], 16;" :: "r"(dst), "l"(src));
}
#define CP_COMMIT() asm volatile("cp.async.commit_group;" ::: "memory")
#define CP_WAIT(n)  asm volatile("cp.async.wait_group %0;" :: "n"(n) : "memory")

// ---------------- K0: build weights (split planes; gamma folded into value) -------
__global__ __launch_bounds__(256) void build_w_kernel(
    const float* __restrict__ qw, const float* __restrict__ qb,
    const float* __restrict__ kw, const float* __restrict__ kb,
    const float* __restrict__ vw, const float* __restrict__ vb,
    const float* __restrict__ gw)
{
    __shared__ float sg[256];
    __shared__ float srow[256];
    int r = blockIdx.x;
    int t = threadIdx.x;
    if (r < 64) {
        if (t < 128) {
            uint32_t h, l;
            split2(qw[r * C_ + 2 * t], qw[r * C_ + 2 * t + 1], h, l);
            *(uint32_t*)&g_Wqkhi[r * C_ + 2 * t] = h;
            *(uint32_t*)&g_Wqklo[r * C_ + 2 * t] = l;
        }
        if (t == 0) g_biasA[r] = qb[r];
    } else if (r < 128) {
        if (t < 128) {
            uint32_t h, l;
            split2(kw[(r - 64) * C_ + 2 * t], kw[(r - 64) * C_ + 2 * t + 1], h, l);
            *(uint32_t*)&g_Wqkhi[r * C_ + 2 * t] = h;
            *(uint32_t*)&g_Wqklo[r * C_ + 2 * t] = l;
        }
        if (t == 0) g_biasA[r] = kb[r - 64];
    } else {
        int o = r - 128;
        sg[t] = gw[o * C_ + t];
        __syncthreads();
        float acc = 0.f;
        #pragma unroll 8
        for (int c2 = 0; c2 < C_; c2++)
            acc = fmaf(sg[c2], vw[c2 * C_ + t], acc);
        srow[t] = acc;
        if (t == 0) {
            float bb = 0.f;
            for (int c2 = 0; c2 < C_; c2++) bb += sg[c2] * vb[c2];
            g_biasA[r] = bb;
        }
        __syncthreads();
        if (t < 128) {
            uint32_t h, l;
            split2(srow[2 * t], srow[2 * t + 1], h, l);
            *(uint32_t*)&g_Wgvhi[o * C_ + 2 * t] = h;
            *(uint32_t*)&g_Wgvlo[o * C_ + 2 * t] = l;
        }
    }
}

// ---------------- xsplit: x[b][c][n] fp32 -> xt[b][n][c] bf16 hi/lo ----------------
__global__ __launch_bounds__(256) void xsplit_kernel(const float* __restrict__ x)
{
    __shared__ float sm[64][65];
    const int b = blockIdx.z, c0 = blockIdx.y * 64, n0 = blockIdx.x * 64;
    const int tid = threadIdx.x;
    const float* xb = x + ((long)b * C_ + c0) * N_ + n0;
    #pragma unroll
    for (int u = 0; u < 4; u++) {
        int f  = tid + u * 256;
        int c  = f >> 4;
        int n4 = (f & 15) * 4;
        float4 v = *(const float4*)&xb[(long)c * N_ + n4];
        sm[c][n4 + 0] = v.x; sm[c][n4 + 1] = v.y;
        sm[c][n4 + 2] = v.z; sm[c][n4 + 3] = v.w;
    }
    __syncthreads();
    const int nl  = tid & 63;
    const int c16 = (tid >> 6) * 16;
    long obase = ((long)b * N_ + n0 + nl) * C_ + c0 + c16;
    uint32_t hw[8], lw[8];
    #pragma unroll
    for (int m = 0; m < 8; m++)
        split2(sm[c16 + 2 * m][nl], sm[c16 + 2 * m + 1][nl], hw[m], lw[m]);
    *(uint4*)&g_xthi[obase]     = make_uint4(hw[0], hw[1], hw[2], hw[3]);
    *(uint4*)&g_xthi[obase + 8] = make_uint4(hw[4], hw[5], hw[6], hw[7]);
    *(uint4*)&g_xtlo[obase]     = make_uint4(lw[0], lw[1], lw[2], lw[3]);
    *(uint4*)&g_xtlo[obase + 8] = make_uint4(lw[4], lw[5], lw[6], lw[7]);
}

// ---------------- zero / reciprocal D ---------------------------------------------
__global__ void zero_d_kernel() {
    int i = blockIdx.x * 256 + threadIdx.x;
    if (i < B_ * N_) g_D[i] = 0.f;
}
__global__ void rcp_d_kernel() {
    int i = blockIdx.x * 256 + threadIdx.x;
    if (i < B_ * N_) g_D[i] = 1.0f / g_D[i];
}

// ---------------- generalized MMA GEMM (128x128 CTA tile, ldmatrix, cp.async) ------
// out[m][n] = sum_k (Ahi[+Alo])[m][k] * (Bhi[+Blo])[n][k]
// MODE 0: fp32 out * oscale + per-m bias
// MODE 1: split bf16 out + per-n bias
// MODE 2: single f16 out = (acc + per-m bias) * rcp[n] * ASCALE   (fused prescale)
// k-stage 32, smem row stride 80B. DEPTH>=3: one sync/stage. DEPTH=2: two syncs.
template<int DEPTH, bool ALO, bool BLO, bool F16, int MODE>
__global__ void __launch_bounds__(256, 2)
gemm3_kernel(int kstages,
             const u16* __restrict__ Ahi, const u16* __restrict__ Alo,
             int arows, int astr,
             const u16* __restrict__ Bhi, const u16* __restrict__ Blo,
             int brows, int bstr,
             float* __restrict__ outF, u16* __restrict__ oHi, u16* __restrict__ oLo,
             int orows, int ostr, const float* __restrict__ bias,
             const float* __restrict__ rcp, float oscale)
{
    constexpr int PLA   = 128 * 80;              // one plane bytes
    constexpr int NA    = ALO ? 2 : 1;
    constexpr int NB    = BLO ? 2 : 1;
    constexpr int ALOO  = PLA;                   // (valid iff ALO)
    constexpr int BHIO  = NA * PLA;
    constexpr int BLOO  = (NA + 1) * PLA;        // (valid iff BLO)
    constexpr int STAGE = (NA + NB) * PLA;
    constexpr int CPT   = (NA + NB) * 2;         // cp16 per thread per stage

    extern __shared__ char smem[];
    const uint32_t sbase = smem_u32(smem);
    const int tid = threadIdx.x;
    const int lane = tid & 31;
    const int wid  = tid >> 5;
    const int wm = wid >> 2;            // 0..1
    const int wn = wid & 3;             // 0..3
    const int b  = blockIdx.z;
    const int m0 = blockIdx.y * 128;
    const int n0 = blockIdx.x * 128;

    const long ab = (long)b * arows + m0;
    const long bb = (long)b * brows + n0;

    auto issue = [&](int t, int s) {
        const int kt = t * 32;
        const uint32_t d0 = sbase + s * STAGE;
        #pragma unroll
        for (int u = 0; u < CPT; u++) {
            int cid = u * 256 + tid;
            int row = cid >> 2;
            int c4  = cid & 3;
            const u16* src;
            uint32_t doff;
            if (row < 128) {
                src = Ahi + (ab + row) * (long)astr;
                doff = row * 80;
            } else if (ALO && row < 256) {
                src = Alo + (ab + row - 128) * (long)astr;
                doff = ALOO + (row - 128) * 80;
            } else if (!BLO || row < NA * 128 + 128) {
                src = Bhi + (bb + row - NA * 128) * (long)bstr;
                doff = BHIO + (row - NA * 128) * 80;
            } else {
                src = Blo + (bb + row - NA * 128 - 128) * (long)bstr;
                doff = BLOO + (row - NA * 128 - 128) * 80;
            }
            cp16(d0 + doff + c4 * 16, src + kt + c4 * 8);
        }
        CP_COMMIT();
    };

    float acc[4][4][4];
    #pragma unroll
    for (int mt = 0; mt < 4; mt++)
        #pragma unroll
        for (int nt = 0; nt < 4; nt++)
            #pragma unroll
            for (int e = 0; e < 4; e++) acc[mt][nt][e] = 0.f;

    const int q  = lane & 3;
    const int r4 = lane >> 2;
    const int g  = lane >> 3;
    const int l7 = lane & 7;
    // ldmatrix lane-address offsets (row stride 80B, conflict-free)
    const uint32_t aoff  = (wm * 64 + l7 + ((g & 1) << 3)) * 80 + ((g >> 1) << 4);
    const uint32_t boff0 = (wn * 32 + ((g >> 1)) * 8 + l7) * 80 + ((g & 1) << 4);
    const uint32_t boff1 = boff0 + 16 * 80;

    auto compute = [&](int s) {
        const uint32_t buf = sbase + s * STAGE;
        #pragma unroll
        for (int h = 0; h < 2; h++) {
            const uint32_t kb = h * 32;
            uint32_t bh[4][2], bl[4][2], r[4];
            ldsm4(r, buf + BHIO + boff0 + kb);
            bh[0][0] = r[0]; bh[0][1] = r[1]; bh[1][0] = r[2]; bh[1][1] = r[3];
            ldsm4(r, buf + BHIO + boff1 + kb);
            bh[2][0] = r[0]; bh[2][1] = r[1]; bh[3][0] = r[2]; bh[3][1] = r[3];
            if (BLO) {
                ldsm4(r, buf + BLOO + boff0 + kb);
                bl[0][0] = r[0]; bl[0][1] = r[1]; bl[1][0] = r[2]; bl[1][1] = r[3];
                ldsm4(r, buf + BLOO + boff1 + kb);
                bl[2][0] = r[0]; bl[2][1] = r[1]; bl[3][0] = r[2]; bl[3][1] = r[3];
            }
            #pragma unroll
            for (int mt = 0; mt < 4; mt++) {
                uint32_t ah[4], al[4];
                ldsm4(ah, buf + aoff + mt * 1280 + kb);
                if (ALO) ldsm4(al, buf + ALOO + aoff + mt * 1280 + kb);
                #pragma unroll
                for (int nt = 0; nt < 4; nt++) {
                    if (F16) {
                        mma_f16(acc[mt][nt], ah[0], ah[1], ah[2], ah[3], bh[nt][0], bh[nt][1]);
                        if (ALO)
                            mma_f16(acc[mt][nt], al[0], al[1], al[2], al[3], bh[nt][0], bh[nt][1]);
                        if (BLO)
                            mma_f16(acc[mt][nt], ah[0], ah[1], ah[2], ah[3], bl[nt][0], bl[nt][1]);
                    } else {
                        mma_bf16(acc[mt][nt], ah[0], ah[1], ah[2], ah[3], bh[nt][0], bh[nt][1]);
                        if (ALO)
                            mma_bf16(acc[mt][nt], al[0], al[1], al[2], al[3], bh[nt][0], bh[nt][1]);
                        if (BLO)
                            mma_bf16(acc[mt][nt], ah[0], ah[1], ah[2], ah[3], bl[nt][0], bl[nt][1]);
                    }
                }
            }
        }
    };

    if (DEPTH >= 3) {
        #pragma unroll
        for (int d = 0; d < DEPTH - 1; d++) issue(d, d);
        for (int t = 0; t < kstages; t++) {
            CP_WAIT(DEPTH - 2);
            __syncthreads();
            if (t + DEPTH - 1 < kstages) issue(t + DEPTH - 1, (t + DEPTH - 1) % DEPTH);
            else CP_COMMIT();
            compute(t % DEPTH);
        }
    } else {
        issue(0, 0);
        for (int t = 0; t < kstages; t++) {
            if (t + 1 < kstages) issue(t + 1, (t + 1) & 1);
            else CP_COMMIT();
            CP_WAIT(1);
            __syncthreads();
            compute(t & 1);
            __syncthreads();
        }
    }

    if (MODE == 0) {
        #pragma unroll
        for (int mt = 0; mt < 4; mt++) {
            int rA = m0 + wm * 64 + mt * 16 + r4;
            float bv0 = bias[rA];
            float bv8 = bias[rA + 8];
            long r0 = ((long)b * orows + rA) * ostr;
            long r8 = r0 + 8L * ostr;
            #pragma unroll
            for (int nt = 0; nt < 4; nt++) {
                int col = n0 + wn * 32 + nt * 8 + q * 2;
                float2 v0, v1;
                v0.x = acc[mt][nt][0] * oscale + bv0;
                v0.y = acc[mt][nt][1] * oscale + bv0;
                v1.x = acc[mt][nt][2] * oscale + bv8;
                v1.y = acc[mt][nt][3] * oscale + bv8;
                *(float2*)&outF[r0 + col] = v0;
                *(float2*)&outF[r8 + col] = v1;
            }
        }
    } else if (MODE == 1) {
        #pragma unroll
        for (int mt = 0; mt < 4; mt++) {
            int rA = m0 + wm * 64 + mt * 16 + r4;
            long r0 = ((long)b * orows + rA) * ostr;
            long r8 = r0 + 8L * ostr;
            #pragma unroll
            for (int nt = 0; nt < 4; nt++) {
                int col = n0 + wn * 32 + nt * 8 + q * 2;
                float bv0 = bias[col];
                float bv1 = bias[col + 1];
                uint32_t h, l;
                split2(acc[mt][nt][0] + bv0, acc[mt][nt][1] + bv1, h, l);
                *(uint32_t*)&oHi[r0 + col] = h;
                *(uint32_t*)&oLo[r0 + col] = l;
                split2(acc[mt][nt][2] + bv0, acc[mt][nt][3] + bv1, h, l);
                *(uint32_t*)&oHi[r8 + col] = h;
                *(uint32_t*)&oLo[r8 + col] = l;
            }
        }
    } else {
        #pragma unroll
        for (int mt = 0; mt < 4; mt++) {
            int rA = m0 + wm * 64 + mt * 16 + r4;
            float bv0 = bias[rA];
            float bv8 = bias[rA + 8];
            long r0 = ((long)b * orows + rA) * ostr;
            long r8 = r0 + 8L * ostr;
            #pragma unroll
            for (int nt = 0; nt < 4; nt++) {
                int col = n0 + wn * 32 + nt * 8 + q * 2;
                float rc0 = rcp[(long)b * N_ + col] * ASCALE;
                float rc1 = rcp[(long)b * N_ + col + 1] * ASCALE;
                uint32_t h;
                asm("cvt.rn.f16x2.f32 %0, %1, %2;" : "=r"(h)
                    : "f"((acc[mt][nt][1] + bv0) * rc1), "f"((acc[mt][nt][0] + bv0) * rc0));
                *(uint32_t*)&oHi[r0 + col] = h;
                asm("cvt.rn.f16x2.f32 %0, %1, %2;" : "=r"(h)
                    : "f"((acc[mt][nt][3] + bv8) * rc1), "f"((acc[mt][nt][2] + bv8) * rc0));
                *(uint32_t*)&oHi[r8 + col] = h;
            }
        }
    }
}

// ---------------- energy: Ef[j][i] = f16(exp(Qt_i . Kt_j)) via MMA -----------------
// A = Kt rows (QKt cols 64..127), B = Qt rows (cols 0..63). k = 64 single-shot.
#define EPL 18432
#define SMEM_E (4 * EPL)          // 73728

__global__ void __launch_bounds__(256, 2) energy_mma_kernel()
{
    extern __shared__ char smem[];
    __shared__ float sD[128];
    const uint32_t sbase = smem_u32(smem);
    const int tid = threadIdx.x;
    const int lane = tid & 31;
    const int wid  = tid >> 5;
    const int wm = wid >> 2;            // j offset wm*64
    const int wn = wid & 3;             // i offset wn*32
    const int b  = blockIdx.z;
    const int i0 = blockIdx.x * 128;
    const int j0 = blockIdx.y * 128;

    if (tid < 128) sD[tid] = 0.f;

    {
        const int p   = tid >> 6;
        const int t64 = tid & 63;
        const u16* gsrc = (p == 0) ? g_QKthi : (p == 1) ? g_QKtlo
                        : (p == 2) ? g_QKthi : g_QKtlo;
        const int coff = (p < 2) ? 64 : 0;
        const long rowbase = (long)b * N_ + ((p < 2) ? j0 : i0);
        const uint32_t pdst = sbase + p * EPL;
        #pragma unroll
        for (int u = 0; u < 16; u++) {
            int cid = u * 64 + t64;
            int row = cid >> 3;
            int c8  = (cid & 7) * 8;
            cp16(pdst + row * 144 + c8 * 2,
                 gsrc + (rowbase + row) * 128 + coff + c8);
        }
        CP_COMMIT();
    }
    CP_WAIT(0);
    __syncthreads();

    float acc[4][4][4];
    #pragma unroll
    for (int mt = 0; mt < 4; mt++)
        #pragma unroll
        for (int nt = 0; nt < 4; nt++)
            #pragma unroll
            for (int e = 0; e < 4; e++) acc[mt][nt][e] = 0.f;

    const int q  = lane & 3;
    const int r4 = lane >> 2;
    const int g  = lane >> 3;
    const int l7 = lane & 7;
    const uint32_t aoff  = (wm * 64 + l7 + ((g & 1) << 3)) * 144 + ((g >> 1) << 4);
    const uint32_t boff0 = (wn * 32 + ((g >> 1)) * 8 + l7) * 144 + ((g & 1) << 4);
    const uint32_t boff1 = boff0 + 16 * 144;

    #pragma unroll
    for (int kc = 0; kc < 4; kc++) {
        const uint32_t kb = kc * 32;
        uint32_t bh[4][2], bl[4][2], r[4];
        ldsm4(r, sbase + 2 * EPL + boff0 + kb);
        bh[0][0] = r[0]; bh[0][1] = r[1]; bh[1][0] = r[2]; bh[1][1] = r[3];
        ldsm4(r, sbase + 2 * EPL + boff1 + kb);
        bh[2][0] = r[0]; bh[2][1] = r[1]; bh[3][0] = r[2]; bh[3][1] = r[3];
        ldsm4(r, sbase + 3 * EPL + boff0 + kb);
        bl[0][0] = r[0]; bl[0][1] = r[1]; bl[1][0] = r[2]; bl[1][1] = r[3];
        ldsm4(r, sbase + 3 * EPL + boff1 + kb);
        bl[2][0] = r[0]; bl[2][1] = r[1]; bl[3][0] = r[2]; bl[3][1] = r[3];
        #pragma unroll
        for (int mt = 0; mt < 4; mt++) {
            uint32_t ah[4], al[4];
            ldsm4(ah, sbase + aoff + mt * 2304 + kb);
            ldsm4(al, sbase + EPL + aoff + mt * 2304 + kb);
            #pragma unroll
            for (int nt = 0; nt < 4; nt++) {
                mma_bf16(acc[mt][nt], ah[0], ah[1], ah[2], ah[3], bh[nt][0], bh[nt][1]);
                mma_bf16(acc[mt][nt], ah[0], ah[1], ah[2], ah[3], bl[nt][0], bl[nt][1]);
                mma_bf16(acc[mt][nt], al[0], al[1], al[2], al[3], bh[nt][0], bh[nt][1]);
            }
        }
    }

    // epilogue: exp, fp16 store, accumulate D over j
    float psum[4][2];
    #pragma unroll
    for (int nt = 0; nt < 4; nt++) { psum[nt][0] = 0.f; psum[nt][1] = 0.f; }

    #pragma unroll
    for (int mt = 0; mt < 4; mt++) {
        int jrow = j0 + wm * 64 + mt * 16 + r4;
        long r0 = ((long)b * N_ + jrow) * N_;
        long r8 = r0 + 8L * N_;
        #pragma unroll
        for (int nt = 0; nt < 4; nt++) {
            int col = i0 + wn * 32 + nt * 8 + 2 * q;
            float e0 = __expf(acc[mt][nt][0]);
            float e1 = __expf(acc[mt][nt][1]);
            float e2 = __expf(acc[mt][nt][2]);
            float e3 = __expf(acc[mt][nt][3]);
            uint32_t p01, p23;
            asm("cvt.rn.f16x2.f32 %0, %1, %2;" : "=r"(p01) : "f"(e1), "f"(e0));
            asm("cvt.rn.f16x2.f32 %0, %1, %2;" : "=r"(p23) : "f"(e3), "f"(e2));
            *(uint32_t*)&g_Ef[r0 + col] = p01;
            *(uint32_t*)&g_Ef[r8 + col] = p23;
            psum[nt][0] += e0 + e2;
            psum[nt][1] += e1 + e3;
        }
    }

    #pragma unroll
    for (int nt = 0; nt < 4; nt++)
        #pragma unroll
        for (int w = 0; w < 2; w++) {
            float v = psum[nt][w];
            v += __shfl_xor_sync(0xffffffffu, v, 4);
            v += __shfl_xor_sync(0xffffffffu, v, 8);
            v += __shfl_xor_sync(0xffffffffu, v, 16);
            if (lane < 4)
                atomicAdd(&sD[wn * 32 + nt * 8 + 2 * lane + w], v);
        }
    __syncthreads();
    if (tid < 128) atomicAdd(&g_D[b * N_ + i0 + tid], sD[tid]);
}

// ---------------- launch ----------------------------------------------------------
extern "C" void kernel_launch(void* const* d_in, const int* in_sizes, int n_in,
                              void* d_out, int out_size)
{
    const float* x  = (const float*)d_in[0];
    const float* qw = (const float*)d_in[1];
    const float* qb = (const float*)d_in[2];
    const float* kw = (const float*)d_in[3];
    const float* kb = (const float*)d_in[4];
    const float* vw = (const float*)d_in[5];
    const float* vb = (const float*)d_in[6];
    const float* gw = (const float*)d_in[7];
    const float* gb = (const float*)d_in[8];
    float* out = (float*)d_out;

    void *pxh, *pxl, *pqkh, *pqkl, *pgvh, *pgvl, *pbias,
         *pQh, *pQl, *pEf, *pAf, *pD;
    cudaGetSymbolAddress(&pxh,  g_xthi);
    cudaGetSymbolAddress(&pxl,  g_xtlo);
    cudaGetSymbolAddress(&pqkh, g_Wqkhi);
    cudaGetSymbolAddress(&pqkl, g_Wqklo);
    cudaGetSymbolAddress(&pgvh, g_Wgvhi);
    cudaGetSymbolAddress(&pgvl, g_Wgvlo);
    cudaGetSymbolAddress(&pbias, g_biasA);
    cudaGetSymbolAddress(&pQh,  g_QKthi);
    cudaGetSymbolAddress(&pQl,  g_QKtlo);
    cudaGetSymbolAddress(&pEf,  g_Ef);
    cudaGetSymbolAddress(&pAf,  g_Af);
    cudaGetSymbolAddress(&pD,   g_D);

    auto kQK  = gemm3_kernel<2, true,  true,  false, 1>;
    auto kGV  = gemm3_kernel<2, true,  true,  false, 2>;
    auto kOUT = gemm3_kernel<4, false, false, true,  0>;
    const int SMEM_QK  = 2 * 4 * 128 * 80;   // 81920
    const int SMEM_OUT = 4 * 2 * 128 * 80;   // 81920

    cudaFuncSetAttribute(kQK,  cudaFuncAttributeMaxDynamicSharedMemorySize, SMEM_QK);
    cudaFuncSetAttribute(kGV,  cudaFuncAttributeMaxDynamicSharedMemorySize, SMEM_QK);
    cudaFuncSetAttribute(kOUT, cudaFuncAttributeMaxDynamicSharedMemorySize, SMEM_OUT);
    cudaFuncSetAttribute(energy_mma_kernel,
                         cudaFuncAttributeMaxDynamicSharedMemorySize, SMEM_E);

    // K0: weight planes (gamma folded into value)
    build_w_kernel<<<384, 256>>>(qw, qb, kw, kb, vw, vb, gw);

    // x -> transposed bf16 planes
    xsplit_kernel<<<dim3(N_ / 64, C_ / 64, B_), 256>>>(x);

    // QKt[b][i][ck] = xt . Wqk^T + bias  (split bf16 out, per-n bias)
    kQK<<<dim3(1, N_ / 128, B_), 256, SMEM_QK>>>(
        C_ / 32,
        (const u16*)pxh, (const u16*)pxl, N_, C_,
        (const u16*)pqkh, (const u16*)pqkl, 0, C_,
        nullptr, (u16*)pQh, (u16*)pQl, N_, 128, (const float*)pbias,
        nullptr, 1.f);

    zero_d_kernel<<<(B_ * N_ + 255) / 256, 256>>>();

    // E plane (fp16) + D sums
    energy_mma_kernel<<<dim3(N_ / 128, N_ / 128, B_), 256, SMEM_E>>>();

    rcp_d_kernel<<<(B_ * N_ + 255) / 256, 256>>>();

    // A plane = f16((Wgv . xt^T + bias) * 1/D * 4096)  (fused prescale, single plane)
    kGV<<<dim3(N_ / 128, C_ / 128, B_), 256, SMEM_QK>>>(
        C_ / 32,
        (const u16*)pgvh, (const u16*)pgvl, 0, C_,
        (const u16*)pxh, (const u16*)pxl, N_, C_,
        nullptr, (u16*)pAf, nullptr, C_, N_, (const float*)pbias + 128,
        (const float*)pD, 1.f);

    // out[b][c][j] = (A . Ef^T) / 4096 + gb   (pure f16 1-term, depth-4 single-sync)
    kOUT<<<dim3(N_ / 128, C_ / 128, B_), 256, SMEM_OUT>>>(
        N_ / 32,
        (const u16*)pAf, nullptr, C_, N_,
        (const u16*)pEf, nullptr, N_, N_,
        out, nullptr, nullptr, C_, N_, gb,
        nullptr, 1.f / ASCALE);
}

// round 14
// speedup vs baseline: 1.2230x; 1.2230x over previous
#include <cuda_runtime.h>
#include <cuda_bf16.h>
#include <cuda_fp16.h>
#include <cstdint>

// Problem constants (fixed shapes from reference)
#define B_  8
#define C_  256
#define CK_ 64
#define N_  2304

typedef unsigned short u16;

// ---------------- scratch (__device__ globals) ------------------------------------
__device__ u16   g_xthi[B_ * N_ * C_];        // x transposed [b][n][c], bf16 hi
__device__ u16   g_xtlo[B_ * N_ * C_];        // lo plane
__device__ u16   g_Wqkhi[128 * C_];           // q(64)+k(64) weights [ck][c]
__device__ u16   g_Wqklo[128 * C_];
__device__ u16   g_Wgvhi[C_ * C_];            // (gamma@value) weights [c_out][c]
__device__ u16   g_Wgvlo[C_ * C_];
__device__ float g_biasA[384];                // qb|kb|gv bias
__device__ u16   g_QKthi[B_ * N_ * 128];      // Qt|Kt [b][i][ck] bf16 hi
__device__ u16   g_QKtlo[B_ * N_ * 128];
__device__ u16   g_Ef[(long)B_ * N_ * N_];    // exp(QK) [b][j][i], single fp16 plane
__device__ u16   g_Ahi[B_ * C_ * N_];         // (GV/D * 4096) fp16 hi plane [b][c][i]
__device__ u16   g_Alo[B_ * C_ * N_];         // fp16 lo plane
__device__ float g_D[B_ * N_];                // row sums over j

#define ASCALE 4096.0f

// ---------------- helpers ----------------------------------------------------------
__device__ __forceinline__ void mma_bf16(float* c,
    uint32_t a0, uint32_t a1, uint32_t a2, uint32_t a3, uint32_t b0, uint32_t b1)
{
    asm volatile(
        "mma.sync.aligned.m16n8k16.row.col.f32.bf16.bf16.f32 "
        "{%0,%1,%2,%3}, {%4,%5,%6,%7}, {%8,%9}, {%0,%1,%2,%3};"
        : "+f"(c[0]), "+f"(c[1]), "+f"(c[2]), "+f"(c[3])
        : "r"(a0), "r"(a1), "r"(a2), "r"(a3), "r"(b0), "r"(b1));
}
__device__ __forceinline__ void mma_f16(float* c,
    uint32_t a0, uint32_t a1, uint32_t a2, uint32_t a3, uint32_t b0, uint32_t b1)
{
    asm volatile(
        "mma.sync.aligned.m16n8k16.row.col.f32.f16.f16.f32 "
        "{%0,%1,%2,%3}, {%4,%5,%6,%7}, {%8,%9}, {%0,%1,%2,%3};"
        : "+f"(c[0]), "+f"(c[1]), "+f"(c[2]), "+f"(c[3])
        : "r"(a0), "r"(a1), "r"(a2), "r"(a3), "r"(b0), "r"(b1));
}
__device__ __forceinline__ void ldsm4(uint32_t* r, uint32_t addr)
{
    asm volatile("ldmatrix.sync.aligned.m8n8.x4.shared.b16 {%0,%1,%2,%3}, [%4];"
        : "=r"(r[0]), "=r"(r[1]), "=r"(r[2]), "=r"(r[3]) : "r"(addr));
}

// split (a,b) into packed bf16x2 hi + lo planes (low half = a)
__device__ __forceinline__ void split2(float a, float b, uint32_t& hi, uint32_t& lo)
{
    uint32_t h;
    asm("cvt.rn.bf16x2.f32 %0, %1, %2;" : "=r"(h) : "f"(b), "f"(a));
    float ha = __uint_as_float(h << 16);
    float hb = __uint_as_float(h & 0xffff0000u);
    float la = a - ha, lb = b - hb;
    uint32_t l;
    asm("cvt.rn.bf16x2.f32 %0, %1, %2;" : "=r"(l) : "f"(lb), "f"(la));
    hi = h; lo = l;
}

// split (a,b) into packed f16x2 hi + lo planes (low half = a)
__device__ __forceinline__ void split2h(float a, float b, uint32_t& hi, uint32_t& lo)
{
    uint32_t h;
    asm("cvt.rn.f16x2.f32 %0, %1, %2;" : "=r"(h) : "f"(b), "f"(a));
    __half2 hv = *reinterpret_cast<__half2*>(&h);
    float ha = __low2float(hv), hb = __high2float(hv);
    uint32_t l;
    asm("cvt.rn.f16x2.f32 %0, %1, %2;" : "=r"(l) : "f"(b - hb), "f"(a - ha));
    hi = h; lo = l;
}

__device__ __forceinline__ uint32_t smem_u32(const void* p) {
    uint32_t a;
    asm("{ .reg .u64 t; cvta.to.shared.u64 t, %1; cvt.u32.u64 %0, t; }" : "=r"(a) : "l"(p));
    return a;
}
__device__ __forceinline__ void cp16(uint32_t dst, const void* src) {
    asm volatile("cp.async.cg.shared.global [%0], [%1], 16;" :: "r"(dst), "l"(src));
}
#define CP_COMMIT() asm volatile("cp.async.commit_group;" ::: "memory")
#define CP_WAIT(n)  asm volatile("cp.async.wait_group %0;" :: "n"(n) : "memory")

// ---------------- K0: build weights (split planes; gamma folded into value) -------
__global__ __launch_bounds__(256) void build_w_kernel(
    const float* __restrict__ qw, const float* __restrict__ qb,
    const float* __restrict__ kw, const float* __restrict__ kb,
    const float* __restrict__ vw, const float* __restrict__ vb,
    const float* __restrict__ gw)
{
    __shared__ float sg[256];
    __shared__ float srow[256];
    int r = blockIdx.x;
    int t = threadIdx.x;
    if (r < 64) {
        if (t < 128) {
            uint32_t h, l;
            split2(qw[r * C_ + 2 * t], qw[r * C_ + 2 * t + 1], h, l);
            *(uint32_t*)&g_Wqkhi[r * C_ + 2 * t] = h;
            *(uint32_t*)&g_Wqklo[r * C_ + 2 * t] = l;
        }
        if (t == 0) g_biasA[r] = qb[r];
    } else if (r < 128) {
        if (t < 128) {
            uint32_t h, l;
            split2(kw[(r - 64) * C_ + 2 * t], kw[(r - 64) * C_ + 2 * t + 1], h, l);
            *(uint32_t*)&g_Wqkhi[r * C_ + 2 * t] = h;
            *(uint32_t*)&g_Wqklo[r * C_ + 2 * t] = l;
        }
        if (t == 0) g_biasA[r] = kb[r - 64];
    } else {
        int o = r - 128;
        sg[t] = gw[o * C_ + t];
        __syncthreads();
        float acc = 0.f;
        #pragma unroll 8
        for (int c2 = 0; c2 < C_; c2++)
            acc = fmaf(sg[c2], vw[c2 * C_ + t], acc);
        srow[t] = acc;
        if (t == 0) {
            float bb = 0.f;
            for (int c2 = 0; c2 < C_; c2++) bb += sg[c2] * vb[c2];
            g_biasA[r] = bb;
        }
        __syncthreads();
        if (t < 128) {
            uint32_t h, l;
            split2(srow[2 * t], srow[2 * t + 1], h, l);
            *(uint32_t*)&g_Wgvhi[o * C_ + 2 * t] = h;
            *(uint32_t*)&g_Wgvlo[o * C_ + 2 * t] = l;
        }
    }
}

// ---------------- xsplit: x[b][c][n] fp32 -> xt[b][n][c] bf16 hi/lo ----------------
__global__ __launch_bounds__(256) void xsplit_kernel(const float* __restrict__ x)
{
    __shared__ float sm[64][65];
    const int b = blockIdx.z, c0 = blockIdx.y * 64, n0 = blockIdx.x * 64;
    const int tid = threadIdx.x;
    const float* xb = x + ((long)b * C_ + c0) * N_ + n0;
    #pragma unroll
    for (int u = 0; u < 4; u++) {
        int f  = tid + u * 256;
        int c  = f >> 4;
        int n4 = (f & 15) * 4;
        float4 v = *(const float4*)&xb[(long)c * N_ + n4];
        sm[c][n4 + 0] = v.x; sm[c][n4 + 1] = v.y;
        sm[c][n4 + 2] = v.z; sm[c][n4 + 3] = v.w;
    }
    __syncthreads();
    const int nl  = tid & 63;
    const int c16 = (tid >> 6) * 16;
    long obase = ((long)b * N_ + n0 + nl) * C_ + c0 + c16;
    uint32_t hw[8], lw[8];
    #pragma unroll
    for (int m = 0; m < 8; m++)
        split2(sm[c16 + 2 * m][nl], sm[c16 + 2 * m + 1][nl], hw[m], lw[m]);
    *(uint4*)&g_xthi[obase]     = make_uint4(hw[0], hw[1], hw[2], hw[3]);
    *(uint4*)&g_xthi[obase + 8] = make_uint4(hw[4], hw[5], hw[6], hw[7]);
    *(uint4*)&g_xtlo[obase]     = make_uint4(lw[0], lw[1], lw[2], lw[3]);
    *(uint4*)&g_xtlo[obase + 8] = make_uint4(lw[4], lw[5], lw[6], lw[7]);
}

// ---------------- zero D -----------------------------------------------------------
__global__ void zero_d_kernel() {
    int i = blockIdx.x * 256 + threadIdx.x;
    if (i < B_ * N_) g_D[i] = 0.f;
}

// ---------------- generalized MMA GEMM (128x128 CTA tile, ldmatrix, cp.async) ------
// out[m][n] = sum_k (Ahi[+Alo])[m][k] * (Bhi[+Blo])[n][k]
// MODE 0: fp32 out * oscale + per-m bias
// MODE 1: split bf16 out + per-n bias
// MODE 2: split f16 out = (acc + per-m bias) * (ASCALE / D[n])   (fused prescale)
// k-stage 32, smem row stride 80B. DEPTH>=3: one sync/stage. DEPTH=2: two syncs.
// cp.async addressing fully hoisted: per thread, c4 = tid&3 is constant and rows
// are (tid>>2) + {0,64} per plane -> one base pointer per plane + 64*stride reg.
template<int DEPTH, bool ALO, bool BLO, bool F16, int MODE>
__global__ void __launch_bounds__(256, 2)
gemm3_kernel(int kstages,
             const u16* __restrict__ Ahi, const u16* __restrict__ Alo,
             int arows, int astr,
             const u16* __restrict__ Bhi, const u16* __restrict__ Blo,
             int brows, int bstr,
             float* __restrict__ outF, u16* __restrict__ oHi, u16* __restrict__ oLo,
             int orows, int ostr, const float* __restrict__ bias,
             const float* __restrict__ dvec, float oscale)
{
    constexpr int PLA   = 128 * 80;              // one plane bytes
    constexpr int NA    = ALO ? 2 : 1;
    constexpr int NB    = BLO ? 2 : 1;
    constexpr int ALOO  = PLA;                   // (valid iff ALO)
    constexpr int BHIO  = NA * PLA;
    constexpr int BLOO  = (NA + 1) * PLA;        // (valid iff BLO)
    constexpr int STAGE = (NA + NB) * PLA;

    extern __shared__ char smem[];
    const uint32_t sbase = smem_u32(smem);
    const int tid = threadIdx.x;
    const int lane = tid & 31;
    const int wid  = tid >> 5;
    const int wm = wid >> 2;            // 0..1
    const int wn = wid & 3;             // 0..3
    const int b  = blockIdx.z;
    const int m0 = blockIdx.y * 128;
    const int n0 = blockIdx.x * 128;

    const long ab = (long)b * arows + m0;
    const long bb = (long)b * brows + n0;

    // hoisted cp.async addressing
    const int r0i = tid >> 2;           // 0..63
    const int c4  = tid & 3;
    const u16* pAh = Ahi + (ab + r0i) * (long)astr + c4 * 8;
    const u16* pAl = ALO ? (Alo + (ab + r0i) * (long)astr + c4 * 8) : pAh;
    const u16* pBh = Bhi + (bb + r0i) * (long)bstr + c4 * 8;
    const u16* pBl = BLO ? (Blo + (bb + r0i) * (long)bstr + c4 * 8) : pBh;
    const long a64 = 64L * astr;
    const long b64 = 64L * bstr;
    const uint32_t dA = (uint32_t)(r0i * 80 + c4 * 16);

    auto issue = [&](int t, int s) {
        const int kt = t * 32;
        const uint32_t d0 = sbase + s * STAGE + dA;
        cp16(d0,                 pAh + kt);
        cp16(d0 + 5120,          pAh + a64 + kt);
        if (ALO) {
            cp16(d0 + ALOO,        pAl + kt);
            cp16(d0 + ALOO + 5120, pAl + a64 + kt);
        }
        cp16(d0 + BHIO,          pBh + kt);
        cp16(d0 + BHIO + 5120,   pBh + b64 + kt);
        if (BLO) {
            cp16(d0 + BLOO,        pBl + kt);
            cp16(d0 + BLOO + 5120, pBl + b64 + kt);
        }
        CP_COMMIT();
    };

    float acc[4][4][4];
    #pragma unroll
    for (int mt = 0; mt < 4; mt++)
        #pragma unroll
        for (int nt = 0; nt < 4; nt++)
            #pragma unroll
            for (int e = 0; e < 4; e++) acc[mt][nt][e] = 0.f;

    const int q  = lane & 3;
    const int r4 = lane >> 2;
    const int g  = lane >> 3;
    const int l7 = lane & 7;
    // ldmatrix lane-address offsets (row stride 80B, conflict-free)
    const uint32_t aoff  = (wm * 64 + l7 + ((g & 1) << 3)) * 80 + ((g >> 1) << 4);
    const uint32_t boff0 = (wn * 32 + ((g >> 1)) * 8 + l7) * 80 + ((g & 1) << 4);
    const uint32_t boff1 = boff0 + 16 * 80;

    auto compute = [&](int s) {
        const uint32_t buf = sbase + s * STAGE;
        #pragma unroll
        for (int h = 0; h < 2; h++) {
            const uint32_t kb = h * 32;
            uint32_t bh[4][2], bl[4][2], r[4];
            ldsm4(r, buf + BHIO + boff0 + kb);
            bh[0][0] = r[0]; bh[0][1] = r[1]; bh[1][0] = r[2]; bh[1][1] = r[3];
            ldsm4(r, buf + BHIO + boff1 + kb);
            bh[2][0] = r[0]; bh[2][1] = r[1]; bh[3][0] = r[2]; bh[3][1] = r[3];
            if (BLO) {
                ldsm4(r, buf + BLOO + boff0 + kb);
                bl[0][0] = r[0]; bl[0][1] = r[1]; bl[1][0] = r[2]; bl[1][1] = r[3];
                ldsm4(r, buf + BLOO + boff1 + kb);
                bl[2][0] = r[0]; bl[2][1] = r[1]; bl[3][0] = r[2]; bl[3][1] = r[3];
            }
            #pragma unroll
            for (int mt = 0; mt < 4; mt++) {
                uint32_t ah[4], al[4];
                ldsm4(ah, buf + aoff + mt * 1280 + kb);
                if (ALO) ldsm4(al, buf + ALOO + aoff + mt * 1280 + kb);
                #pragma unroll
                for (int nt = 0; nt < 4; nt++) {
                    if (F16) {
                        mma_f16(acc[mt][nt], ah[0], ah[1], ah[2], ah[3], bh[nt][0], bh[nt][1]);
                        if (ALO)
                            mma_f16(acc[mt][nt], al[0], al[1], al[2], al[3], bh[nt][0], bh[nt][1]);
                        if (BLO)
                            mma_f16(acc[mt][nt], ah[0], ah[1], ah[2], ah[3], bl[nt][0], bl[nt][1]);
                    } else {
                        mma_bf16(acc[mt][nt], ah[0], ah[1], ah[2], ah[3], bh[nt][0], bh[nt][1]);
                        if (ALO)
                            mma_bf16(acc[mt][nt], al[0], al[1], al[2], al[3], bh[nt][0], bh[nt][1]);
                        if (BLO)
                            mma_bf16(acc[mt][nt], ah[0], ah[1], ah[2], ah[3], bl[nt][0], bl[nt][1]);
                    }
                }
            }
        }
    };

    if (DEPTH >= 3) {
        #pragma unroll
        for (int d = 0; d < DEPTH - 1; d++) issue(d, d);
        for (int t = 0; t < kstages; t++) {
            CP_WAIT(DEPTH - 2);
            __syncthreads();
            if (t + DEPTH - 1 < kstages) issue(t + DEPTH - 1, (t + DEPTH - 1) % DEPTH);
            else CP_COMMIT();
            compute(t % DEPTH);
        }
    } else {
        issue(0, 0);
        for (int t = 0; t < kstages; t++) {
            if (t + 1 < kstages) issue(t + 1, (t + 1) & 1);
            else CP_COMMIT();
            CP_WAIT(1);
            __syncthreads();
            compute(t & 1);
            __syncthreads();
        }
    }

    if (MODE == 0) {
        #pragma unroll
        for (int mt = 0; mt < 4; mt++) {
            int rA = m0 + wm * 64 + mt * 16 + r4;
            float bv0 = bias[rA];
            float bv8 = bias[rA + 8];
            long r0 = ((long)b * orows + rA) * ostr;
            long r8 = r0 + 8L * ostr;
            #pragma unroll
            for (int nt = 0; nt < 4; nt++) {
                int col = n0 + wn * 32 + nt * 8 + q * 2;
                float2 v0, v1;
                v0.x = acc[mt][nt][0] * oscale + bv0;
                v0.y = acc[mt][nt][1] * oscale + bv0;
                v1.x = acc[mt][nt][2] * oscale + bv8;
                v1.y = acc[mt][nt][3] * oscale + bv8;
                *(float2*)&outF[r0 + col] = v0;
                *(float2*)&outF[r8 + col] = v1;
            }
        }
    } else if (MODE == 1) {
        #pragma unroll
        for (int mt = 0; mt < 4; mt++) {
            int rA = m0 + wm * 64 + mt * 16 + r4;
            long r0 = ((long)b * orows + rA) * ostr;
            long r8 = r0 + 8L * ostr;
            #pragma unroll
            for (int nt = 0; nt < 4; nt++) {
                int col = n0 + wn * 32 + nt * 8 + q * 2;
                float bv0 = bias[col];
                float bv1 = bias[col + 1];
                uint32_t h, l;
                split2(acc[mt][nt][0] + bv0, acc[mt][nt][1] + bv1, h, l);
                *(uint32_t*)&oHi[r0 + col] = h;
                *(uint32_t*)&oLo[r0 + col] = l;
                split2(acc[mt][nt][2] + bv0, acc[mt][nt][3] + bv1, h, l);
                *(uint32_t*)&oHi[r8 + col] = h;
                *(uint32_t*)&oLo[r8 + col] = l;
            }
        }
    } else {
        #pragma unroll
        for (int mt = 0; mt < 4; mt++) {
            int rA = m0 + wm * 64 + mt * 16 + r4;
            float bv0 = bias[rA];
            float bv8 = bias[rA + 8];
            long r0 = ((long)b * orows + rA) * ostr;
            long r8 = r0 + 8L * ostr;
            #pragma unroll
            for (int nt = 0; nt < 4; nt++) {
                int col = n0 + wn * 32 + nt * 8 + q * 2;
                float rc0 = __fdividef(ASCALE, dvec[(long)b * N_ + col]);
                float rc1 = __fdividef(ASCALE, dvec[(long)b * N_ + col + 1]);
                uint32_t h, l;
                split2h((acc[mt][nt][0] + bv0) * rc0, (acc[mt][nt][1] + bv0) * rc1, h, l);
                *(uint32_t*)&oHi[r0 + col] = h;
                *(uint32_t*)&oLo[r0 + col] = l;
                split2h((acc[mt][nt][2] + bv8) * rc0, (acc[mt][nt][3] + bv8) * rc1, h, l);
                *(uint32_t*)&oHi[r8 + col] = h;
                *(uint32_t*)&oLo[r8 + col] = l;
            }
        }
    }
}

// ---------------- energy: Ef[j][i] = f16(exp(Qt_i . Kt_j)) via MMA -----------------
// A = Kt rows (QKt cols 64..127), B = Qt rows (cols 0..63). k = 64 single-shot.
#define EPL 18432
#define SMEM_E (4 * EPL)          // 73728

__global__ void __launch_bounds__(256, 2) energy_mma_kernel()
{
    extern __shared__ char smem[];
    __shared__ float sD[128];
    const uint32_t sbase = smem_u32(smem);
    const int tid = threadIdx.x;
    const int lane = tid & 31;
    const int wid  = tid >> 5;
    const int wm = wid >> 2;            // j offset wm*64
    const int wn = wid & 3;             // i offset wn*32
    const int b  = blockIdx.z;
    const int i0 = blockIdx.x * 128;
    const int j0 = blockIdx.y * 128;

    if (tid < 128) sD[tid] = 0.f;

    {
        const int p   = tid >> 6;
        const int t64 = tid & 63;
        const u16* gsrc = (p == 0) ? g_QKthi : (p == 1) ? g_QKtlo
                        : (p == 2) ? g_QKthi : g_QKtlo;
        const int coff = (p < 2) ? 64 : 0;
        const long rowbase = (long)b * N_ + ((p < 2) ? j0 : i0);
        const uint32_t pdst = sbase + p * EPL;
        #pragma unroll
        for (int u = 0; u < 16; u++) {
            int cid = u * 64 + t64;
            int row = cid >> 3;
            int c8  = (cid & 7) * 8;
            cp16(pdst + row * 144 + c8 * 2,
                 gsrc + (rowbase + row) * 128 + coff + c8);
        }
        CP_COMMIT();
    }
    CP_WAIT(0);
    __syncthreads();

    float acc[4][4][4];
    #pragma unroll
    for (int mt = 0; mt < 4; mt++)
        #pragma unroll
        for (int nt = 0; nt < 4; nt++)
            #pragma unroll
            for (int e = 0; e < 4; e++) acc[mt][nt][e] = 0.f;

    const int q  = lane & 3;
    const int r4 = lane >> 2;
    const int g  = lane >> 3;
    const int l7 = lane & 7;
    const uint32_t aoff  = (wm * 64 + l7 + ((g & 1) << 3)) * 144 + ((g >> 1) << 4);
    const uint32_t boff0 = (wn * 32 + ((g >> 1)) * 8 + l7) * 144 + ((g & 1) << 4);
    const uint32_t boff1 = boff0 + 16 * 144;

    #pragma unroll
    for (int kc = 0; kc < 4; kc++) {
        const uint32_t kb = kc * 32;
        uint32_t bh[4][2], bl[4][2], r[4];
        ldsm4(r, sbase + 2 * EPL + boff0 + kb);
        bh[0][0] = r[0]; bh[0][1] = r[1]; bh[1][0] = r[2]; bh[1][1] = r[3];
        ldsm4(r, sbase + 2 * EPL + boff1 + kb);
        bh[2][0] = r[0]; bh[2][1] = r[1]; bh[3][0] = r[2]; bh[3][1] = r[3];
        ldsm4(r, sbase + 3 * EPL + boff0 + kb);
        bl[0][0] = r[0]; bl[0][1] = r[1]; bl[1][0] = r[2]; bl[1][1] = r[3];
        ldsm4(r, sbase + 3 * EPL + boff1 + kb);
        bl[2][0] = r[0]; bl[2][1] = r[1]; bl[3][0] = r[2]; bl[3][1] = r[3];
        #pragma unroll
        for (int mt = 0; mt < 4; mt++) {
            uint32_t ah[4], al[4];
            ldsm4(ah, sbase + aoff + mt * 2304 + kb);
            ldsm4(al, sbase + EPL + aoff + mt * 2304 + kb);
            #pragma unroll
            for (int nt = 0; nt < 4; nt++) {
                mma_bf16(acc[mt][nt], ah[0], ah[1], ah[2], ah[3], bh[nt][0], bh[nt][1]);
                mma_bf16(acc[mt][nt], ah[0], ah[1], ah[2], ah[3], bl[nt][0], bl[nt][1]);
                mma_bf16(acc[mt][nt], al[0], al[1], al[2], al[3], bh[nt][0], bh[nt][1]);
            }
        }
    }

    // epilogue: exp, fp16 store, accumulate D over j
    float psum[4][2];
    #pragma unroll
    for (int nt = 0; nt < 4; nt++) { psum[nt][0] = 0.f; psum[nt][1] = 0.f; }

    #pragma unroll
    for (int mt = 0; mt < 4; mt++) {
        int jrow = j0 + wm * 64 + mt * 16 + r4;
        long r0 = ((long)b * N_ + jrow) * N_;
        long r8 = r0 + 8L * N_;
        #pragma unroll
        for (int nt = 0; nt < 4; nt++) {
            int col = i0 + wn * 32 + nt * 8 + 2 * q;
            float e0 = __expf(acc[mt][nt][0]);
            float e1 = __expf(acc[mt][nt][1]);
            float e2 = __expf(acc[mt][nt][2]);
            float e3 = __expf(acc[mt][nt][3]);
            uint32_t p01, p23;
            asm("cvt.rn.f16x2.f32 %0, %1, %2;" : "=r"(p01) : "f"(e1), "f"(e0));
            asm("cvt.rn.f16x2.f32 %0, %1, %2;" : "=r"(p23) : "f"(e3), "f"(e2));
            *(uint32_t*)&g_Ef[r0 + col] = p01;
            *(uint32_t*)&g_Ef[r8 + col] = p23;
            psum[nt][0] += e0 + e2;
            psum[nt][1] += e1 + e3;
        }
    }

    #pragma unroll
    for (int nt = 0; nt < 4; nt++)
        #pragma unroll
        for (int w = 0; w < 2; w++) {
            float v = psum[nt][w];
            v += __shfl_xor_sync(0xffffffffu, v, 4);
            v += __shfl_xor_sync(0xffffffffu, v, 8);
            v += __shfl_xor_sync(0xffffffffu, v, 16);
            if (lane < 4)
                atomicAdd(&sD[wn * 32 + nt * 8 + 2 * lane + w], v);
        }
    __syncthreads();
    if (tid < 128) atomicAdd(&g_D[b * N_ + i0 + tid], sD[tid]);
}

// ---------------- launch ----------------------------------------------------------
extern "C" void kernel_launch(void* const* d_in, const int* in_sizes, int n_in,
                              void* d_out, int out_size)
{
    const float* x  = (const float*)d_in[0];
    const float* qw = (const float*)d_in[1];
    const float* qb = (const float*)d_in[2];
    const float* kw = (const float*)d_in[3];
    const float* kb = (const float*)d_in[4];
    const float* vw = (const float*)d_in[5];
    const float* vb = (const float*)d_in[6];
    const float* gw = (const float*)d_in[7];
    const float* gb = (const float*)d_in[8];
    float* out = (float*)d_out;

    void *pxh, *pxl, *pqkh, *pqkl, *pgvh, *pgvl, *pbias,
         *pQh, *pQl, *pEf, *pAh, *pAl, *pD;
    cudaGetSymbolAddress(&pxh,  g_xthi);
    cudaGetSymbolAddress(&pxl,  g_xtlo);
    cudaGetSymbolAddress(&pqkh, g_Wqkhi);
    cudaGetSymbolAddress(&pqkl, g_Wqklo);
    cudaGetSymbolAddress(&pgvh, g_Wgvhi);
    cudaGetSymbolAddress(&pgvl, g_Wgvlo);
    cudaGetSymbolAddress(&pbias, g_biasA);
    cudaGetSymbolAddress(&pQh,  g_QKthi);
    cudaGetSymbolAddress(&pQl,  g_QKtlo);
    cudaGetSymbolAddress(&pEf,  g_Ef);
    cudaGetSymbolAddress(&pAh,  g_Ahi);
    cudaGetSymbolAddress(&pAl,  g_Alo);
    cudaGetSymbolAddress(&pD,   g_D);

    auto kQK  = gemm3_kernel<2, true,  true,  false, 1>;
    auto kGV  = gemm3_kernel<2, true,  true,  false, 2>;
    auto kOUT = gemm3_kernel<3, true,  false, true,  0>;
    const int SMEM_QK  = 2 * 4 * 128 * 80;   // 81920
    const int SMEM_OUT = 3 * 3 * 128 * 80;   // 92160

    cudaFuncSetAttribute(kQK,  cudaFuncAttributeMaxDynamicSharedMemorySize, SMEM_QK);
    cudaFuncSetAttribute(kGV,  cudaFuncAttributeMaxDynamicSharedMemorySize, SMEM_QK);
    cudaFuncSetAttribute(kOUT, cudaFuncAttributeMaxDynamicSharedMemorySize, SMEM_OUT);
    cudaFuncSetAttribute(energy_mma_kernel,
                         cudaFuncAttributeMaxDynamicSharedMemorySize, SMEM_E);

    // K0: weight planes (gamma folded into value)
    build_w_kernel<<<384, 256>>>(qw, qb, kw, kb, vw, vb, gw);

    // x -> transposed bf16 planes
    xsplit_kernel<<<dim3(N_ / 64, C_ / 64, B_), 256>>>(x);

    // QKt[b][i][ck] = xt . Wqk^T + bias  (split bf16 out, per-n bias)
    kQK<<<dim3(1, N_ / 128, B_), 256, SMEM_QK>>>(
        C_ / 32,
        (const u16*)pxh, (const u16*)pxl, N_, C_,
        (const u16*)pqkh, (const u16*)pqkl, 0, C_,
        nullptr, (u16*)pQh, (u16*)pQl, N_, 128, (const float*)pbias,
        nullptr, 1.f);

    zero_d_kernel<<<(B_ * N_ + 255) / 256, 256>>>();

    // E plane (fp16) + D sums
    energy_mma_kernel<<<dim3(N_ / 128, N_ / 128, B_), 256, SMEM_E>>>();

    // A planes = f16 split((Wgv . xt^T + bias) * ASCALE / D)  (fused prescale + rcp)
    kGV<<<dim3(N_ / 128, C_ / 128, B_), 256, SMEM_QK>>>(
        C_ / 32,
        (const u16*)pgvh, (const u16*)pgvl, 0, C_,
        (const u16*)pxh, (const u16*)pxl, N_, C_,
        nullptr, (u16*)pAh, (u16*)pAl, C_, N_, (const float*)pbias + 128,
        (const float*)pD, 1.f);

    // out[b][c][j] = (A . Ef^T) / 4096 + gb   (f16 2-term, depth-3 single-sync)
    kOUT<<<dim3(N_ / 128, C_ / 128, B_), 256, SMEM_OUT>>>(
        N_ / 32,
        (const u16*)pAh, (const u16*)pAl, C_, N_,
        (const u16*)pEf, nullptr, N_, N_,
        out, nullptr, nullptr, C_, N_, gb,
        nullptr, 1.f / ASCALE);
}

// round 15
// speedup vs baseline: 1.3398x; 1.0955x over previous
#include <cuda_runtime.h>
#include <cuda_bf16.h>
#include <cuda_fp16.h>
#include <cstdint>

// Problem constants (fixed shapes from reference)
#define B_  8
#define C_  256
#define CK_ 64
#define N_  2304

typedef unsigned short u16;

// ---------------- scratch (__device__ globals) ------------------------------------
__device__ u16   g_xthi[B_ * N_ * C_];        // x transposed [b][n][c], bf16 hi
__device__ u16   g_xtlo[B_ * N_ * C_];        // lo plane
__device__ u16   g_Wqkhi[128 * C_];           // q(64)+k(64) weights [ck][c]
__device__ u16   g_Wqklo[128 * C_];
__device__ u16   g_Wgvhi[C_ * C_];            // (gamma@value) weights [c_out][c]
__device__ u16   g_Wgvlo[C_ * C_];
__device__ float g_biasA[384];                // qb|kb|gv bias
__device__ u16   g_QKtf[B_ * N_ * 128];       // Qt|Kt [b][i][ck], single f16 plane
__device__ u16   g_Ef[(long)B_ * N_ * N_];    // exp(QK) [b][j][i], single fp16 plane
__device__ u16   g_Ahi[B_ * C_ * N_];         // (GV/D * 4096) fp16 hi plane [b][c][i]
__device__ u16   g_Alo[B_ * C_ * N_];         // fp16 lo plane
__device__ float g_D[B_ * N_];                // row sums over j

#define ASCALE 4096.0f

// ---------------- helpers ----------------------------------------------------------
__device__ __forceinline__ void mma_bf16(float* c,
    uint32_t a0, uint32_t a1, uint32_t a2, uint32_t a3, uint32_t b0, uint32_t b1)
{
    asm volatile(
        "mma.sync.aligned.m16n8k16.row.col.f32.bf16.bf16.f32 "
        "{%0,%1,%2,%3}, {%4,%5,%6,%7}, {%8,%9}, {%0,%1,%2,%3};"
        : "+f"(c[0]), "+f"(c[1]), "+f"(c[2]), "+f"(c[3])
        : "r"(a0), "r"(a1), "r"(a2), "r"(a3), "r"(b0), "r"(b1));
}
__device__ __forceinline__ void mma_f16(float* c,
    uint32_t a0, uint32_t a1, uint32_t a2, uint32_t a3, uint32_t b0, uint32_t b1)
{
    asm volatile(
        "mma.sync.aligned.m16n8k16.row.col.f32.f16.f16.f32 "
        "{%0,%1,%2,%3}, {%4,%5,%6,%7}, {%8,%9}, {%0,%1,%2,%3};"
        : "+f"(c[0]), "+f"(c[1]), "+f"(c[2]), "+f"(c[3])
        : "r"(a0), "r"(a1), "r"(a2), "r"(a3), "r"(b0), "r"(b1));
}
__device__ __forceinline__ void ldsm4(uint32_t* r, uint32_t addr)
{
    asm volatile("ldmatrix.sync.aligned.m8n8.x4.shared.b16 {%0,%1,%2,%3}, [%4];"
        : "=r"(r[0]), "=r"(r[1]), "=r"(r[2]), "=r"(r[3]) : "r"(addr));
}

// split (a,b) into packed bf16x2 hi + lo planes (low half = a)
__device__ __forceinline__ void split2(float a, float b, uint32_t& hi, uint32_t& lo)
{
    uint32_t h;
    asm("cvt.rn.bf16x2.f32 %0, %1, %2;" : "=r"(h) : "f"(b), "f"(a));
    float ha = __uint_as_float(h << 16);
    float hb = __uint_as_float(h & 0xffff0000u);
    float la = a - ha, lb = b - hb;
    uint32_t l;
    asm("cvt.rn.bf16x2.f32 %0, %1, %2;" : "=r"(l) : "f"(lb), "f"(la));
    hi = h; lo = l;
}

// split (a,b) into packed f16x2 hi + lo planes (low half = a)
__device__ __forceinline__ void split2h(float a, float b, uint32_t& hi, uint32_t& lo)
{
    uint32_t h;
    asm("cvt.rn.f16x2.f32 %0, %1, %2;" : "=r"(h) : "f"(b), "f"(a));
    __half2 hv = *reinterpret_cast<__half2*>(&h);
    float ha = __low2float(hv), hb = __high2float(hv);
    uint32_t l;
    asm("cvt.rn.f16x2.f32 %0, %1, %2;" : "=r"(l) : "f"(b - hb), "f"(a - ha));
    hi = h; lo = l;
}

__device__ __forceinline__ uint32_t smem_u32(const void* p) {
    uint32_t a;
    asm("{ .reg .u64 t; cvta.to.shared.u64 t, %1; cvt.u32.u64 %0, t; }" : "=r"(a) : "l"(p));
    return a;
}
__device__ __forceinline__ void cp16(uint32_t dst, const void* src) {
    asm volatile("cp.async.cg.shared.global [%0], [%1], 16;" :: "r"(dst), "l"(src));
}
#define CP_COMMIT() asm volatile("cp.async.commit_group;" ::: "memory")
#define CP_WAIT(n)  asm volatile("cp.async.wait_group %0;" :: "n"(n) : "memory")

// ---------------- K0: build weights (split planes; gamma folded into value) -------
// Blocks 0..71 additionally zero g_D (folds the old zero_d launch).
__global__ __launch_bounds__(256) void build_w_kernel(
    const float* __restrict__ qw, const float* __restrict__ qb,
    const float* __restrict__ kw, const float* __restrict__ kb,
    const float* __restrict__ vw, const float* __restrict__ vb,
    const float* __restrict__ gw)
{
    __shared__ float sg[256];
    __shared__ float srow[256];
    int r = blockIdx.x;
    int t = threadIdx.x;
    if (r < 72) g_D[r * 256 + t] = 0.f;
    if (r < 64) {
        if (t < 128) {
            uint32_t h, l;
            split2(qw[r * C_ + 2 * t], qw[r * C_ + 2 * t + 1], h, l);
            *(uint32_t*)&g_Wqkhi[r * C_ + 2 * t] = h;
            *(uint32_t*)&g_Wqklo[r * C_ + 2 * t] = l;
        }
        if (t == 0) g_biasA[r] = qb[r];
    } else if (r < 128) {
        if (t < 128) {
            uint32_t h, l;
            split2(kw[(r - 64) * C_ + 2 * t], kw[(r - 64) * C_ + 2 * t + 1], h, l);
            *(uint32_t*)&g_Wqkhi[r * C_ + 2 * t] = h;
            *(uint32_t*)&g_Wqklo[r * C_ + 2 * t] = l;
        }
        if (t == 0) g_biasA[r] = kb[r - 64];
    } else {
        int o = r - 128;
        sg[t] = gw[o * C_ + t];
        __syncthreads();
        float acc = 0.f;
        #pragma unroll 8
        for (int c2 = 0; c2 < C_; c2++)
            acc = fmaf(sg[c2], vw[c2 * C_ + t], acc);
        srow[t] = acc;
        if (t == 0) {
            float bb = 0.f;
            for (int c2 = 0; c2 < C_; c2++) bb += sg[c2] * vb[c2];
            g_biasA[r] = bb;
        }
        __syncthreads();
        if (t < 128) {
            uint32_t h, l;
            split2(srow[2 * t], srow[2 * t + 1], h, l);
            *(uint32_t*)&g_Wgvhi[o * C_ + 2 * t] = h;
            *(uint32_t*)&g_Wgvlo[o * C_ + 2 * t] = l;
        }
    }
}

// ---------------- xsplit: x[b][c][n] fp32 -> xt[b][n][c] bf16 hi/lo ----------------
__global__ __launch_bounds__(256) void xsplit_kernel(const float* __restrict__ x)
{
    __shared__ float sm[64][65];
    const int b = blockIdx.z, c0 = blockIdx.y * 64, n0 = blockIdx.x * 64;
    const int tid = threadIdx.x;
    const float* xb = x + ((long)b * C_ + c0) * N_ + n0;
    #pragma unroll
    for (int u = 0; u < 4; u++) {
        int f  = tid + u * 256;
        int c  = f >> 4;
        int n4 = (f & 15) * 4;
        float4 v = *(const float4*)&xb[(long)c * N_ + n4];
        sm[c][n4 + 0] = v.x; sm[c][n4 + 1] = v.y;
        sm[c][n4 + 2] = v.z; sm[c][n4 + 3] = v.w;
    }
    __syncthreads();
    const int nl  = tid & 63;
    const int c16 = (tid >> 6) * 16;
    long obase = ((long)b * N_ + n0 + nl) * C_ + c0 + c16;
    uint32_t hw[8], lw[8];
    #pragma unroll
    for (int m = 0; m < 8; m++)
        split2(sm[c16 + 2 * m][nl], sm[c16 + 2 * m + 1][nl], hw[m], lw[m]);
    *(uint4*)&g_xthi[obase]     = make_uint4(hw[0], hw[1], hw[2], hw[3]);
    *(uint4*)&g_xthi[obase + 8] = make_uint4(hw[4], hw[5], hw[6], hw[7]);
    *(uint4*)&g_xtlo[obase]     = make_uint4(lw[0], lw[1], lw[2], lw[3]);
    *(uint4*)&g_xtlo[obase + 8] = make_uint4(lw[4], lw[5], lw[6], lw[7]);
}

// ---------------- generalized MMA GEMM (128x128 CTA tile, ldmatrix, cp.async) ------
// out[m][n] = sum_k (Ahi[+Alo])[m][k] * (Bhi[+Blo])[n][k]
// MODE 0: fp32 out * oscale + per-m bias
// MODE 1: split bf16 out + per-n bias
// MODE 2: split f16 out = (acc + per-m bias) * (ASCALE / D[n])   (fused prescale)
// MODE 3: single f16 out = acc + per-n bias
// k-stage 32, smem row stride 80B. DEPTH>=3: one sync/stage. DEPTH=2: two syncs.
template<int DEPTH, bool ALO, bool BLO, bool F16, int MODE>
__global__ void __launch_bounds__(256, 2)
gemm3_kernel(int kstages,
             const u16* __restrict__ Ahi, const u16* __restrict__ Alo,
             int arows, int astr,
             const u16* __restrict__ Bhi, const u16* __restrict__ Blo,
             int brows, int bstr,
             float* __restrict__ outF, u16* __restrict__ oHi, u16* __restrict__ oLo,
             int orows, int ostr, const float* __restrict__ bias,
             const float* __restrict__ dvec, float oscale)
{
    constexpr int PLA   = 128 * 80;              // one plane bytes
    constexpr int NA    = ALO ? 2 : 1;
    constexpr int NB    = BLO ? 2 : 1;
    constexpr int ALOO  = PLA;                   // (valid iff ALO)
    constexpr int BHIO  = NA * PLA;
    constexpr int BLOO  = (NA + 1) * PLA;        // (valid iff BLO)
    constexpr int STAGE = (NA + NB) * PLA;

    extern __shared__ char smem[];
    const uint32_t sbase = smem_u32(smem);
    const int tid = threadIdx.x;
    const int lane = tid & 31;
    const int wid  = tid >> 5;
    const int wm = wid >> 2;            // 0..1
    const int wn = wid & 3;             // 0..3
    const int b  = blockIdx.z;
    const int m0 = blockIdx.y * 128;
    const int n0 = blockIdx.x * 128;

    const long ab = (long)b * arows + m0;
    const long bb = (long)b * brows + n0;

    // hoisted cp.async addressing
    const int r0i = tid >> 2;           // 0..63
    const int c4  = tid & 3;
    const u16* pAh = Ahi + (ab + r0i) * (long)astr + c4 * 8;
    const u16* pAl = ALO ? (Alo + (ab + r0i) * (long)astr + c4 * 8) : pAh;
    const u16* pBh = Bhi + (bb + r0i) * (long)bstr + c4 * 8;
    const u16* pBl = BLO ? (Blo + (bb + r0i) * (long)bstr + c4 * 8) : pBh;
    const long a64 = 64L * astr;
    const long b64 = 64L * bstr;
    const uint32_t dA = (uint32_t)(r0i * 80 + c4 * 16);

    auto issue = [&](int t, int s) {
        const int kt = t * 32;
        const uint32_t d0 = sbase + s * STAGE + dA;
        cp16(d0,                 pAh + kt);
        cp16(d0 + 5120,          pAh + a64 + kt);
        if (ALO) {
            cp16(d0 + ALOO,        pAl + kt);
            cp16(d0 + ALOO + 5120, pAl + a64 + kt);
        }
        cp16(d0 + BHIO,          pBh + kt);
        cp16(d0 + BHIO + 5120,   pBh + b64 + kt);
        if (BLO) {
            cp16(d0 + BLOO,        pBl + kt);
            cp16(d0 + BLOO + 5120, pBl + b64 + kt);
        }
        CP_COMMIT();
    };

    float acc[4][4][4];
    #pragma unroll
    for (int mt = 0; mt < 4; mt++)
        #pragma unroll
        for (int nt = 0; nt < 4; nt++)
            #pragma unroll
            for (int e = 0; e < 4; e++) acc[mt][nt][e] = 0.f;

    const int q  = lane & 3;
    const int r4 = lane >> 2;
    const int g  = lane >> 3;
    const int l7 = lane & 7;
    // ldmatrix lane-address offsets (row stride 80B, conflict-free)
    const uint32_t aoff  = (wm * 64 + l7 + ((g & 1) << 3)) * 80 + ((g >> 1) << 4);
    const uint32_t boff0 = (wn * 32 + ((g >> 1)) * 8 + l7) * 80 + ((g & 1) << 4);
    const uint32_t boff1 = boff0 + 16 * 80;

    auto compute = [&](int s) {
        const uint32_t buf = sbase + s * STAGE;
        #pragma unroll
        for (int h = 0; h < 2; h++) {
            const uint32_t kb = h * 32;
            uint32_t bh[4][2], bl[4][2], r[4];
            ldsm4(r, buf + BHIO + boff0 + kb);
            bh[0][0] = r[0]; bh[0][1] = r[1]; bh[1][0] = r[2]; bh[1][1] = r[3];
            ldsm4(r, buf + BHIO + boff1 + kb);
            bh[2][0] = r[0]; bh[2][1] = r[1]; bh[3][0] = r[2]; bh[3][1] = r[3];
            if (BLO) {
                ldsm4(r, buf + BLOO + boff0 + kb);
                bl[0][0] = r[0]; bl[0][1] = r[1]; bl[1][0] = r[2]; bl[1][1] = r[3];
                ldsm4(r, buf + BLOO + boff1 + kb);
                bl[2][0] = r[0]; bl[2][1] = r[1]; bl[3][0] = r[2]; bl[3][1] = r[3];
            }
            #pragma unroll
            for (int mt = 0; mt < 4; mt++) {
                uint32_t ah[4], al[4];
                ldsm4(ah, buf + aoff + mt * 1280 + kb);
                if (ALO) ldsm4(al, buf + ALOO + aoff + mt * 1280 + kb);
                #pragma unroll
                for (int nt = 0; nt < 4; nt++) {
                    if (F16) {
                        mma_f16(acc[mt][nt], ah[0], ah[1], ah[2], ah[3], bh[nt][0], bh[nt][1]);
                        if (ALO)
                            mma_f16(acc[mt][nt], al[0], al[1], al[2], al[3], bh[nt][0], bh[nt][1]);
                        if (BLO)
                            mma_f16(acc[mt][nt], ah[0], ah[1], ah[2], ah[3], bl[nt][0], bl[nt][1]);
                    } else {
                        mma_bf16(acc[mt][nt], ah[0], ah[1], ah[2], ah[3], bh[nt][0], bh[nt][1]);
                        if (ALO)
                            mma_bf16(acc[mt][nt], al[0], al[1], al[2], al[3], bh[nt][0], bh[nt][1]);
                        if (BLO)
                            mma_bf16(acc[mt][nt], ah[0], ah[1], ah[2], ah[3], bl[nt][0], bl[nt][1]);
                    }
                }
            }
        }
    };

    if (DEPTH >= 3) {
        #pragma unroll
        for (int d = 0; d < DEPTH - 1; d++) issue(d, d);
        for (int t = 0; t < kstages; t++) {
            CP_WAIT(DEPTH - 2);
            __syncthreads();
            if (t + DEPTH - 1 < kstages) issue(t + DEPTH - 1, (t + DEPTH - 1) % DEPTH);
            else CP_COMMIT();
            compute(t % DEPTH);
        }
    } else {
        issue(0, 0);
        for (int t = 0; t < kstages; t++) {
            if (t + 1 < kstages) issue(t + 1, (t + 1) & 1);
            else CP_COMMIT();
            CP_WAIT(1);
            __syncthreads();
            compute(t & 1);
            __syncthreads();
        }
    }

    if (MODE == 0) {
        #pragma unroll
        for (int mt = 0; mt < 4; mt++) {
            int rA = m0 + wm * 64 + mt * 16 + r4;
            float bv0 = bias[rA];
            float bv8 = bias[rA + 8];
            long r0 = ((long)b * orows + rA) * ostr;
            long r8 = r0 + 8L * ostr;
            #pragma unroll
            for (int nt = 0; nt < 4; nt++) {
                int col = n0 + wn * 32 + nt * 8 + q * 2;
                float2 v0, v1;
                v0.x = acc[mt][nt][0] * oscale + bv0;
                v0.y = acc[mt][nt][1] * oscale + bv0;
                v1.x = acc[mt][nt][2] * oscale + bv8;
                v1.y = acc[mt][nt][3] * oscale + bv8;
                *(float2*)&outF[r0 + col] = v0;
                *(float2*)&outF[r8 + col] = v1;
            }
        }
    } else if (MODE == 1) {
        #pragma unroll
        for (int mt = 0; mt < 4; mt++) {
            int rA = m0 + wm * 64 + mt * 16 + r4;
            long r0 = ((long)b * orows + rA) * ostr;
            long r8 = r0 + 8L * ostr;
            #pragma unroll
            for (int nt = 0; nt < 4; nt++) {
                int col = n0 + wn * 32 + nt * 8 + q * 2;
                float bv0 = bias[col];
                float bv1 = bias[col + 1];
                uint32_t h, l;
                split2(acc[mt][nt][0] + bv0, acc[mt][nt][1] + bv1, h, l);
                *(uint32_t*)&oHi[r0 + col] = h;
                *(uint32_t*)&oLo[r0 + col] = l;
                split2(acc[mt][nt][2] + bv0, acc[mt][nt][3] + bv1, h, l);
                *(uint32_t*)&oHi[r8 + col] = h;
                *(uint32_t*)&oLo[r8 + col] = l;
            }
        }
    } else if (MODE == 2) {
        #pragma unroll
        for (int mt = 0; mt < 4; mt++) {
            int rA = m0 + wm * 64 + mt * 16 + r4;
            float bv0 = bias[rA];
            float bv8 = bias[rA + 8];
            long r0 = ((long)b * orows + rA) * ostr;
            long r8 = r0 + 8L * ostr;
            #pragma unroll
            for (int nt = 0; nt < 4; nt++) {
                int col = n0 + wn * 32 + nt * 8 + q * 2;
                float rc0 = __fdividef(ASCALE, dvec[(long)b * N_ + col]);
                float rc1 = __fdividef(ASCALE, dvec[(long)b * N_ + col + 1]);
                uint32_t h, l;
                split2h((acc[mt][nt][0] + bv0) * rc0, (acc[mt][nt][1] + bv0) * rc1, h, l);
                *(uint32_t*)&oHi[r0 + col] = h;
                *(uint32_t*)&oLo[r0 + col] = l;
                split2h((acc[mt][nt][2] + bv8) * rc0, (acc[mt][nt][3] + bv8) * rc1, h, l);
                *(uint32_t*)&oHi[r8 + col] = h;
                *(uint32_t*)&oLo[r8 + col] = l;
            }
        }
    } else {
        #pragma unroll
        for (int mt = 0; mt < 4; mt++) {
            int rA = m0 + wm * 64 + mt * 16 + r4;
            long r0 = ((long)b * orows + rA) * ostr;
            long r8 = r0 + 8L * ostr;
            #pragma unroll
            for (int nt = 0; nt < 4; nt++) {
                int col = n0 + wn * 32 + nt * 8 + q * 2;
                float bv0 = bias[col];
                float bv1 = bias[col + 1];
                uint32_t h;
                asm("cvt.rn.f16x2.f32 %0, %1, %2;" : "=r"(h)
                    : "f"(acc[mt][nt][1] + bv1), "f"(acc[mt][nt][0] + bv0));
                *(uint32_t*)&oHi[r0 + col] = h;
                asm("cvt.rn.f16x2.f32 %0, %1, %2;" : "=r"(h)
                    : "f"(acc[mt][nt][3] + bv1), "f"(acc[mt][nt][2] + bv0));
                *(uint32_t*)&oHi[r8 + col] = h;
            }
        }
    }
}

// ---------------- energy: Ef[j][i] = f16(exp(Qt_i . Kt_j)), 1-term f16 MMA ---------
// A = Kt rows (QKtf cols 64..127), B = Qt rows (cols 0..63). k = 64 single-shot.
#define EPL 18432
#define SMEM_E (2 * EPL)          // 36864

__global__ void __launch_bounds__(256, 2) energy_mma_kernel()
{
    extern __shared__ char smem[];
    __shared__ float sD[128];
    const uint32_t sbase = smem_u32(smem);
    const int tid = threadIdx.x;
    const int lane = tid & 31;
    const int wid  = tid >> 5;
    const int wm = wid >> 2;            // j offset wm*64
    const int wn = wid & 3;             // i offset wn*32
    const int b  = blockIdx.z;
    const int i0 = blockIdx.x * 128;
    const int j0 = blockIdx.y * 128;

    if (tid < 128) sD[tid] = 0.f;

    // load 2 planes: p0 = Kt (A), p1 = Qt (B)
    {
        const int p    = tid >> 7;
        const int t128 = tid & 127;
        const int coff = (p == 0) ? 64 : 0;
        const long rowbase = (long)b * N_ + ((p == 0) ? j0 : i0);
        const uint32_t pdst = sbase + p * EPL;
        #pragma unroll
        for (int u = 0; u < 8; u++) {
            int cid = u * 128 + t128;   // 0..1023
            int row = cid >> 3;
            int c8  = (cid & 7) * 8;
            cp16(pdst + row * 144 + c8 * 2,
                 g_QKtf + (rowbase + row) * 128 + coff + c8);
        }
        CP_COMMIT();
    }
    CP_WAIT(0);
    __syncthreads();

    float acc[4][4][4];
    #pragma unroll
    for (int mt = 0; mt < 4; mt++)
        #pragma unroll
        for (int nt = 0; nt < 4; nt++)
            #pragma unroll
            for (int e = 0; e < 4; e++) acc[mt][nt][e] = 0.f;

    const int q  = lane & 3;
    const int r4 = lane >> 2;
    const int g  = lane >> 3;
    const int l7 = lane & 7;
    const uint32_t aoff  = (wm * 64 + l7 + ((g & 1) << 3)) * 144 + ((g >> 1) << 4);
    const uint32_t boff0 = (wn * 32 + ((g >> 1)) * 8 + l7) * 144 + ((g & 1) << 4);
    const uint32_t boff1 = boff0 + 16 * 144;

    #pragma unroll
    for (int kc = 0; kc < 4; kc++) {
        const uint32_t kb = kc * 32;
        uint32_t bh[4][2], r[4];
        ldsm4(r, sbase + EPL + boff0 + kb);
        bh[0][0] = r[0]; bh[0][1] = r[1]; bh[1][0] = r[2]; bh[1][1] = r[3];
        ldsm4(r, sbase + EPL + boff1 + kb);
        bh[2][0] = r[0]; bh[2][1] = r[1]; bh[3][0] = r[2]; bh[3][1] = r[3];
        #pragma unroll
        for (int mt = 0; mt < 4; mt++) {
            uint32_t ah[4];
            ldsm4(ah, sbase + aoff + mt * 2304 + kb);
            #pragma unroll
            for (int nt = 0; nt < 4; nt++)
                mma_f16(acc[mt][nt], ah[0], ah[1], ah[2], ah[3], bh[nt][0], bh[nt][1]);
        }
    }

    // epilogue: exp, fp16 store, accumulate D over j
    float psum[4][2];
    #pragma unroll
    for (int nt = 0; nt < 4; nt++) { psum[nt][0] = 0.f; psum[nt][1] = 0.f; }

    #pragma unroll
    for (int mt = 0; mt < 4; mt++) {
        int jrow = j0 + wm * 64 + mt * 16 + r4;
        long r0 = ((long)b * N_ + jrow) * N_;
        long r8 = r0 + 8L * N_;
        #pragma unroll
        for (int nt = 0; nt < 4; nt++) {
            int col = i0 + wn * 32 + nt * 8 + 2 * q;
            float e0 = __expf(acc[mt][nt][0]);
            float e1 = __expf(acc[mt][nt][1]);
            float e2 = __expf(acc[mt][nt][2]);
            float e3 = __expf(acc[mt][nt][3]);
            uint32_t p01, p23;
            asm("cvt.rn.f16x2.f32 %0, %1, %2;" : "=r"(p01) : "f"(e1), "f"(e0));
            asm("cvt.rn.f16x2.f32 %0, %1, %2;" : "=r"(p23) : "f"(e3), "f"(e2));
            *(uint32_t*)&g_Ef[r0 + col] = p01;
            *(uint32_t*)&g_Ef[r8 + col] = p23;
            psum[nt][0] += e0 + e2;
            psum[nt][1] += e1 + e3;
        }
    }

    #pragma unroll
    for (int nt = 0; nt < 4; nt++)
        #pragma unroll
        for (int w = 0; w < 2; w++) {
            float v = psum[nt][w];
            v += __shfl_xor_sync(0xffffffffu, v, 4);
            v += __shfl_xor_sync(0xffffffffu, v, 8);
            v += __shfl_xor_sync(0xffffffffu, v, 16);
            if (lane < 4)
                atomicAdd(&sD[wn * 32 + nt * 8 + 2 * lane + w], v);
        }
    __syncthreads();
    if (tid < 128) atomicAdd(&g_D[b * N_ + i0 + tid], sD[tid]);
}

// ---------------- launch ----------------------------------------------------------
extern "C" void kernel_launch(void* const* d_in, const int* in_sizes, int n_in,
                              void* d_out, int out_size)
{
    const float* x  = (const float*)d_in[0];
    const float* qw = (const float*)d_in[1];
    const float* qb = (const float*)d_in[2];
    const float* kw = (const float*)d_in[3];
    const float* kb = (const float*)d_in[4];
    const float* vw = (const float*)d_in[5];
    const float* vb = (const float*)d_in[6];
    const float* gw = (const float*)d_in[7];
    const float* gb = (const float*)d_in[8];
    float* out = (float*)d_out;

    void *pxh, *pxl, *pqkh, *pqkl, *pgvh, *pgvl, *pbias,
         *pQf, *pEf, *pAh, *pAl, *pD;
    cudaGetSymbolAddress(&pxh,  g_xthi);
    cudaGetSymbolAddress(&pxl,  g_xtlo);
    cudaGetSymbolAddress(&pqkh, g_Wqkhi);
    cudaGetSymbolAddress(&pqkl, g_Wqklo);
    cudaGetSymbolAddress(&pgvh, g_Wgvhi);
    cudaGetSymbolAddress(&pgvl, g_Wgvlo);
    cudaGetSymbolAddress(&pbias, g_biasA);
    cudaGetSymbolAddress(&pQf,  g_QKtf);
    cudaGetSymbolAddress(&pEf,  g_Ef);
    cudaGetSymbolAddress(&pAh,  g_Ahi);
    cudaGetSymbolAddress(&pAl,  g_Alo);
    cudaGetSymbolAddress(&pD,   g_D);

    auto kQK  = gemm3_kernel<2, true,  true,  false, 3>;
    auto kGV  = gemm3_kernel<2, true,  true,  false, 2>;
    auto kOUT = gemm3_kernel<3, true,  false, true,  0>;
    const int SMEM_QK  = 2 * 4 * 128 * 80;   // 81920
    const int SMEM_OUT = 3 * 3 * 128 * 80;   // 92160

    cudaFuncSetAttribute(kQK,  cudaFuncAttributeMaxDynamicSharedMemorySize, SMEM_QK);
    cudaFuncSetAttribute(kGV,  cudaFuncAttributeMaxDynamicSharedMemorySize, SMEM_QK);
    cudaFuncSetAttribute(kOUT, cudaFuncAttributeMaxDynamicSharedMemorySize, SMEM_OUT);
    cudaFuncSetAttribute(energy_mma_kernel,
                         cudaFuncAttributeMaxDynamicSharedMemorySize, SMEM_E);

    // K0: weight planes (gamma folded into value) + zero D
    build_w_kernel<<<384, 256>>>(qw, qb, kw, kb, vw, vb, gw);

    // x -> transposed bf16 planes
    xsplit_kernel<<<dim3(N_ / 64, C_ / 64, B_), 256>>>(x);

    // QKtf[b][i][ck] = xt . Wqk^T + bias  (single f16 out, per-n bias)
    kQK<<<dim3(1, N_ / 128, B_), 256, SMEM_QK>>>(
        C_ / 32,
        (const u16*)pxh, (const u16*)pxl, N_, C_,
        (const u16*)pqkh, (const u16*)pqkl, 0, C_,
        nullptr, (u16*)pQf, nullptr, N_, 128, (const float*)pbias,
        nullptr, 1.f);

    // E plane (fp16) + D sums  (1-term f16 MMA)
    energy_mma_kernel<<<dim3(N_ / 128, N_ / 128, B_), 256, SMEM_E>>>();

    // A planes = f16 split((Wgv . xt^T + bias) * ASCALE / D)  (fused prescale + rcp)
    kGV<<<dim3(N_ / 128, C_ / 128, B_), 256, SMEM_QK>>>(
        C_ / 32,
        (const u16*)pgvh, (const u16*)pgvl, 0, C_,
        (const u16*)pxh, (const u16*)pxl, N_, C_,
        nullptr, (u16*)pAh, (u16*)pAl, C_, N_, (const float*)pbias + 128,
        (const float*)pD, 1.f);

    // out[b][c][j] = (A . Ef^T) / 4096 + gb   (f16 2-term, depth-3 single-sync)
    kOUT<<<dim3(N_ / 128, C_ / 128, B_), 256, SMEM_OUT>>>(
        N_ / 32,
        (const u16*)pAh, (const u16*)pAl, C_, N_,
        (const u16*)pEf, nullptr, N_, N_,
        out, nullptr, nullptr, C_, N_, gb,
        nullptr, 1.f / ASCALE);
}

// round 17
// speedup vs baseline: 1.7822x; 1.3301x over previous
#include <cuda_runtime.h>
#include <cuda_bf16.h>
#include <cuda_fp16.h>
#include <cstdint>

// Problem constants (fixed shapes from reference)
#define B_  8
#define C_  256
#define CK_ 64
#define N_  2304

typedef unsigned short u16;

// ---------------- scratch (__device__ globals) ------------------------------------
__device__ u16   g_xthi[B_ * N_ * C_];        // x transposed [b][n][c], bf16 hi
__device__ u16   g_xtlo[B_ * N_ * C_];        // lo plane
__device__ u16   g_Wqkhi[128 * C_];           // q(64)+k(64) weights [ck][c]
__device__ u16   g_Wqklo[128 * C_];
__device__ u16   g_Wgvhi[C_ * C_];            // (gamma@value) weights [c_out][c]
__device__ u16   g_Wgvlo[C_ * C_];
__device__ float g_biasA[384];                // qb|kb|gv bias
__device__ u16   g_QKtf[B_ * N_ * 128];       // Qt|Kt [b][i][ck], single f16 plane
__device__ u16   g_Ef[(long)B_ * N_ * N_];    // exp(QK) [b][j][i], single fp16 plane
__device__ u16   g_Af[B_ * C_ * N_];          // (GV/D * 4096), single fp16 plane
__device__ float g_D[B_ * N_];                // row sums over j

#define ASCALE 4096.0f

// ---------------- helpers ----------------------------------------------------------
__device__ __forceinline__ void mma_bf16(float* c,
    uint32_t a0, uint32_t a1, uint32_t a2, uint32_t a3, uint32_t b0, uint32_t b1)
{
    asm volatile(
        "mma.sync.aligned.m16n8k16.row.col.f32.bf16.bf16.f32 "
        "{%0,%1,%2,%3}, {%4,%5,%6,%7}, {%8,%9}, {%0,%1,%2,%3};"
        : "+f"(c[0]), "+f"(c[1]), "+f"(c[2]), "+f"(c[3])
        : "r"(a0), "r"(a1), "r"(a2), "r"(a3), "r"(b0), "r"(b1));
}
__device__ __forceinline__ void mma_f16(float* c,
    uint32_t a0, uint32_t a1, uint32_t a2, uint32_t a3, uint32_t b0, uint32_t b1)
{
    asm volatile(
        "mma.sync.aligned.m16n8k16.row.col.f32.f16.f16.f32 "
        "{%0,%1,%2,%3}, {%4,%5,%6,%7}, {%8,%9}, {%0,%1,%2,%3};"
        : "+f"(c[0]), "+f"(c[1]), "+f"(c[2]), "+f"(c[3])
        : "r"(a0), "r"(a1), "r"(a2), "r"(a3), "r"(b0), "r"(b1));
}
__device__ __forceinline__ void ldsm4(uint32_t* r, uint32_t addr)
{
    asm volatile("ldmatrix.sync.aligned.m8n8.x4.shared.b16 {%0,%1,%2,%3}, [%4];"
        : "=r"(r[0]), "=r"(r[1]), "=r"(r[2]), "=r"(r[3]) : "r"(addr));
}

// split (a,b) into packed bf16x2 hi + lo planes (low half = a)
__device__ __forceinline__ void split2(float a, float b, uint32_t& hi, uint32_t& lo)
{
    uint32_t h;
    asm("cvt.rn.bf16x2.f32 %0, %1, %2;" : "=r"(h) : "f"(b), "f"(a));
    float ha = __uint_as_float(h << 16);
    float hb = __uint_as_float(h & 0xffff0000u);
    float la = a - ha, lb = b - hb;
    uint32_t l;
    asm("cvt.rn.bf16x2.f32 %0, %1, %2;" : "=r"(l) : "f"(lb), "f"(la));
    hi = h; lo = l;
}

__device__ __forceinline__ uint32_t smem_u32(const void* p) {
    uint32_t a;
    asm("{ .reg .u64 t; cvta.to.shared.u64 t, %1; cvt.u32.u64 %0, t; }" : "=r"(a) : "l"(p));
    return a;
}
__device__ __forceinline__ void cp16(uint32_t dst, const void* src) {
    asm volatile("cp.async.cg.shared.global [%0], [%1], 16;" :: "r"(dst), "l"(src));
}
#define CP_COMMIT() asm volatile("cp.async.commit_group;" ::: "memory")
#define CP_WAIT(n)  asm volatile("cp.async.wait_group %0;" :: "n"(n) : "memory")

// ---------------- K0: build weights (split planes; gamma folded into value) -------
// Blocks 0..71 additionally zero g_D (folds the old zero_d launch).
__global__ __launch_bounds__(256) void build_w_kernel(
    const float* __restrict__ qw, const float* __restrict__ qb,
    const float* __restrict__ kw, const float* __restrict__ kb,
    const float* __restrict__ vw, const float* __restrict__ vb,
    const float* __restrict__ gw)
{
    __shared__ float sg[256];
    __shared__ float srow[256];
    int r = blockIdx.x;
    int t = threadIdx.x;
    if (r < 72) g_D[r * 256 + t] = 0.f;
    if (r < 64) {
        if (t < 128) {
            uint32_t h, l;
            split2(qw[r * C_ + 2 * t], qw[r * C_ + 2 * t + 1], h, l);
            *(uint32_t*)&g_Wqkhi[r * C_ + 2 * t] = h;
            *(uint32_t*)&g_Wqklo[r * C_ + 2 * t] = l;
        }
        if (t == 0) g_biasA[r] = qb[r];
    } else if (r < 128) {
        if (t < 128) {
            uint32_t h, l;
            split2(kw[(r - 64) * C_ + 2 * t], kw[(r - 64) * C_ + 2 * t + 1], h, l);
            *(uint32_t*)&g_Wqkhi[r * C_ + 2 * t] = h;
            *(uint32_t*)&g_Wqklo[r * C_ + 2 * t] = l;
        }
        if (t == 0) g_biasA[r] = kb[r - 64];
    } else {
        int o = r - 128;
        sg[t] = gw[o * C_ + t];
        __syncthreads();
        float acc = 0.f;
        #pragma unroll 8
        for (int c2 = 0; c2 < C_; c2++)
            acc = fmaf(sg[c2], vw[c2 * C_ + t], acc);
        srow[t] = acc;
        if (t == 0) {
            float bb = 0.f;
            for (int c2 = 0; c2 < C_; c2++) bb += sg[c2] * vb[c2];
            g_biasA[r] = bb;
        }
        __syncthreads();
        if (t < 128) {
            uint32_t h, l;
            split2(srow[2 * t], srow[2 * t + 1], h, l);
            *(uint32_t*)&g_Wgvhi[o * C_ + 2 * t] = h;
            *(uint32_t*)&g_Wgvlo[o * C_ + 2 * t] = l;
        }
    }
}

// ---------------- xsplit: x[b][c][n] fp32 -> xt[b][n][c] bf16 hi/lo ----------------
__global__ __launch_bounds__(256) void xsplit_kernel(const float* __restrict__ x)
{
    __shared__ float sm[64][65];
    const int b = blockIdx.z, c0 = blockIdx.y * 64, n0 = blockIdx.x * 64;
    const int tid = threadIdx.x;
    const float* xb = x + ((long)b * C_ + c0) * N_ + n0;
    #pragma unroll
    for (int u = 0; u < 4; u++) {
        int f  = tid + u * 256;
        int c  = f >> 4;
        int n4 = (f & 15) * 4;
        float4 v = *(const float4*)&xb[(long)c * N_ + n4];
        sm[c][n4 + 0] = v.x; sm[c][n4 + 1] = v.y;
        sm[c][n4 + 2] = v.z; sm[c][n4 + 3] = v.w;
    }
    __syncthreads();
    const int nl  = tid & 63;
    const int c16 = (tid >> 6) * 16;
    long obase = ((long)b * N_ + n0 + nl) * C_ + c0 + c16;
    uint32_t hw[8], lw[8];
    #pragma unroll
    for (int m = 0; m < 8; m++)
        split2(sm[c16 + 2 * m][nl], sm[c16 + 2 * m + 1][nl], hw[m], lw[m]);
    *(uint4*)&g_xthi[obase]     = make_uint4(hw[0], hw[1], hw[2], hw[3]);
    *(uint4*)&g_xthi[obase + 8] = make_uint4(hw[4], hw[5], hw[6], hw[7]);
    *(uint4*)&g_xtlo[obase]     = make_uint4(lw[0], lw[1], lw[2], lw[3]);
    *(uint4*)&g_xtlo[obase + 8] = make_uint4(lw[4], lw[5], lw[6], lw[7]);
}

// ---------------- generalized MMA GEMM (128x128 CTA tile, ldmatrix, cp.async) ------
// out[m][n] = sum_k (Ahi[+Alo])[m][k] * (Bhi[+Blo])[n][k]
// MODE 3: single f16 out = acc + per-n bias
// MODE 4: single f16 out = (acc + per-m bias) * (ASCALE / D[n])   (fused prescale)
// k-stage 32, smem row stride 80B, DEPTH=2.
template<int DEPTH, bool ALO, bool BLO, bool F16, int MODE>
__global__ void __launch_bounds__(256, 2)
gemm3_kernel(int kstages,
             const u16* __restrict__ Ahi, const u16* __restrict__ Alo,
             int arows, int astr,
             const u16* __restrict__ Bhi, const u16* __restrict__ Blo,
             int brows, int bstr,
             float* __restrict__ outF, u16* __restrict__ oHi, u16* __restrict__ oLo,
             int orows, int ostr, const float* __restrict__ bias,
             const float* __restrict__ dvec, float oscale)
{
    constexpr int PLA   = 128 * 80;              // one plane bytes
    constexpr int NA    = ALO ? 2 : 1;
    constexpr int NB    = BLO ? 2 : 1;
    constexpr int ALOO  = PLA;                   // (valid iff ALO)
    constexpr int BHIO  = NA * PLA;
    constexpr int BLOO  = (NA + 1) * PLA;        // (valid iff BLO)
    constexpr int STAGE = (NA + NB) * PLA;

    extern __shared__ char smem[];
    const uint32_t sbase = smem_u32(smem);
    const int tid = threadIdx.x;
    const int lane = tid & 31;
    const int wid  = tid >> 5;
    const int wm = wid >> 2;            // 0..1
    const int wn = wid & 3;             // 0..3
    const int b  = blockIdx.z;
    const int m0 = blockIdx.y * 128;
    const int n0 = blockIdx.x * 128;

    const long ab = (long)b * arows + m0;
    const long bb = (long)b * brows + n0;

    // hoisted cp.async addressing
    const int r0i = tid >> 2;           // 0..63
    const int c4  = tid & 3;
    const u16* pAh = Ahi + (ab + r0i) * (long)astr + c4 * 8;
    const u16* pAl = ALO ? (Alo + (ab + r0i) * (long)astr + c4 * 8) : pAh;
    const u16* pBh = Bhi + (bb + r0i) * (long)bstr + c4 * 8;
    const u16* pBl = BLO ? (Blo + (bb + r0i) * (long)bstr + c4 * 8) : pBh;
    const long a64 = 64L * astr;
    const long b64 = 64L * bstr;
    const uint32_t dA = (uint32_t)(r0i * 80 + c4 * 16);

    auto issue = [&](int t, int s) {
        const int kt = t * 32;
        const uint32_t d0 = sbase + s * STAGE + dA;
        cp16(d0,                 pAh + kt);
        cp16(d0 + 5120,          pAh + a64 + kt);
        if (ALO) {
            cp16(d0 + ALOO,        pAl + kt);
            cp16(d0 + ALOO + 5120, pAl + a64 + kt);
        }
        cp16(d0 + BHIO,          pBh + kt);
        cp16(d0 + BHIO + 5120,   pBh + b64 + kt);
        if (BLO) {
            cp16(d0 + BLOO,        pBl + kt);
            cp16(d0 + BLOO + 5120, pBl + b64 + kt);
        }
        CP_COMMIT();
    };

    float acc[4][4][4];
    #pragma unroll
    for (int mt = 0; mt < 4; mt++)
        #pragma unroll
        for (int nt = 0; nt < 4; nt++)
            #pragma unroll
            for (int e = 0; e < 4; e++) acc[mt][nt][e] = 0.f;

    const int q  = lane & 3;
    const int r4 = lane >> 2;
    const int g  = lane >> 3;
    const int l7 = lane & 7;
    // ldmatrix lane-address offsets (row stride 80B, conflict-free)
    const uint32_t aoff  = (wm * 64 + l7 + ((g & 1) << 3)) * 80 + ((g >> 1) << 4);
    const uint32_t boff0 = (wn * 32 + ((g >> 1)) * 8 + l7) * 80 + ((g & 1) << 4);
    const uint32_t boff1 = boff0 + 16 * 80;

    auto compute = [&](int s) {
        const uint32_t buf = sbase + s * STAGE;
        #pragma unroll
        for (int h = 0; h < 2; h++) {
            const uint32_t kb = h * 32;
            uint32_t bh[4][2], bl[4][2], r[4];
            ldsm4(r, buf + BHIO + boff0 + kb);
            bh[0][0] = r[0]; bh[0][1] = r[1]; bh[1][0] = r[2]; bh[1][1] = r[3];
            ldsm4(r, buf + BHIO + boff1 + kb);
            bh[2][0] = r[0]; bh[2][1] = r[1]; bh[3][0] = r[2]; bh[3][1] = r[3];
            if (BLO) {
                ldsm4(r, buf + BLOO + boff0 + kb);
                bl[0][0] = r[0]; bl[0][1] = r[1]; bl[1][0] = r[2]; bl[1][1] = r[3];
                ldsm4(r, buf + BLOO + boff1 + kb);
                bl[2][0] = r[0]; bl[2][1] = r[1]; bl[3][0] = r[2]; bl[3][1] = r[3];
            }
            #pragma unroll
            for (int mt = 0; mt < 4; mt++) {
                uint32_t ah[4], al[4];
                ldsm4(ah, buf + aoff + mt * 1280 + kb);
                if (ALO) ldsm4(al, buf + ALOO + aoff + mt * 1280 + kb);
                #pragma unroll
                for (int nt = 0; nt < 4; nt++) {
                    if (F16) {
                        mma_f16(acc[mt][nt], ah[0], ah[1], ah[2], ah[3], bh[nt][0], bh[nt][1]);
                        if (ALO)
                            mma_f16(acc[mt][nt], al[0], al[1], al[2], al[3], bh[nt][0], bh[nt][1]);
                        if (BLO)
                            mma_f16(acc[mt][nt], ah[0], ah[1], ah[2], ah[3], bl[nt][0], bl[nt][1]);
                    } else {
                        mma_bf16(acc[mt][nt], ah[0], ah[1], ah[2], ah[3], bh[nt][0], bh[nt][1]);
                        if (ALO)
                            mma_bf16(acc[mt][nt], al[0], al[1], al[2], al[3], bh[nt][0], bh[nt][1]);
                        if (BLO)
                            mma_bf16(acc[mt][nt], ah[0], ah[1], ah[2], ah[3], bl[nt][0], bl[nt][1]);
                    }
                }
            }
        }
    };

    issue(0, 0);
    for (int t = 0; t < kstages; t++) {
        if (t + 1 < kstages) issue(t + 1, (t + 1) & 1);
        else CP_COMMIT();
        CP_WAIT(1);
        __syncthreads();
        compute(t & 1);
        __syncthreads();
    }

    if (MODE == 3) {
        #pragma unroll
        for (int mt = 0; mt < 4; mt++) {
            int rA = m0 + wm * 64 + mt * 16 + r4;
            long r0 = ((long)b * orows + rA) * ostr;
            long r8 = r0 + 8L * ostr;
            #pragma unroll
            for (int nt = 0; nt < 4; nt++) {
                int col = n0 + wn * 32 + nt * 8 + q * 2;
                float bv0 = bias[col];
                float bv1 = bias[col + 1];
                uint32_t h;
                asm("cvt.rn.f16x2.f32 %0, %1, %2;" : "=r"(h)
                    : "f"(acc[mt][nt][1] + bv1), "f"(acc[mt][nt][0] + bv0));
                *(uint32_t*)&oHi[r0 + col] = h;
                asm("cvt.rn.f16x2.f32 %0, %1, %2;" : "=r"(h)
                    : "f"(acc[mt][nt][3] + bv1), "f"(acc[mt][nt][2] + bv0));
                *(uint32_t*)&oHi[r8 + col] = h;
            }
        }
    } else {
        #pragma unroll
        for (int mt = 0; mt < 4; mt++) {
            int rA = m0 + wm * 64 + mt * 16 + r4;
            float bv0 = bias[rA];
            float bv8 = bias[rA + 8];
            long r0 = ((long)b * orows + rA) * ostr;
            long r8 = r0 + 8L * ostr;
            #pragma unroll
            for (int nt = 0; nt < 4; nt++) {
                int col = n0 + wn * 32 + nt * 8 + q * 2;
                float rc0 = __fdividef(ASCALE, dvec[(long)b * N_ + col]);
                float rc1 = __fdividef(ASCALE, dvec[(long)b * N_ + col + 1]);
                uint32_t h;
                asm("cvt.rn.f16x2.f32 %0, %1, %2;" : "=r"(h)
                    : "f"((acc[mt][nt][1] + bv0) * rc1), "f"((acc[mt][nt][0] + bv0) * rc0));
                *(uint32_t*)&oHi[r0 + col] = h;
                asm("cvt.rn.f16x2.f32 %0, %1, %2;" : "=r"(h)
                    : "f"((acc[mt][nt][3] + bv8) * rc1), "f"((acc[mt][nt][2] + bv8) * rc0));
                *(uint32_t*)&oHi[r8 + col] = h;
            }
        }
    }
}

// ---------------- energy: Ef[j][i] = f16(exp(Qt_i . Kt_j)), 1-term f16 MMA ---------
// A = Kt rows (QKtf cols 64..127), B = Qt rows (cols 0..63). k = 64 single-shot.
#define EPL 18432
#define SMEM_E (2 * EPL)          // 36864

__global__ void __launch_bounds__(256, 2) energy_mma_kernel()
{
    extern __shared__ char smem[];
    __shared__ float sD[128];
    const uint32_t sbase = smem_u32(smem);
    const int tid = threadIdx.x;
    const int lane = tid & 31;
    const int wid  = tid >> 5;
    const int wm = wid >> 2;            // j offset wm*64
    const int wn = wid & 3;             // i offset wn*32
    const int b  = blockIdx.z;
    const int i0 = blockIdx.x * 128;
    const int j0 = blockIdx.y * 128;

    if (tid < 128) sD[tid] = 0.f;

    // load 2 planes: p0 = Kt (A), p1 = Qt (B)
    {
        const int p    = tid >> 7;
        const int t128 = tid & 127;
        const int coff = (p == 0) ? 64 : 0;
        const long rowbase = (long)b * N_ + ((p == 0) ? j0 : i0);
        const uint32_t pdst = sbase + p * EPL;
        #pragma unroll
        for (int u = 0; u < 8; u++) {
            int cid = u * 128 + t128;   // 0..1023
            int row = cid >> 3;
            int c8  = (cid & 7) * 8;
            cp16(pdst + row * 144 + c8 * 2,
                 g_QKtf + (rowbase + row) * 128 + coff + c8);
        }
        CP_COMMIT();
    }
    CP_WAIT(0);
    __syncthreads();

    float acc[4][4][4];
    #pragma unroll
    for (int mt = 0; mt < 4; mt++)
        #pragma unroll
        for (int nt = 0; nt < 4; nt++)
            #pragma unroll
            for (int e = 0; e < 4; e++) acc[mt][nt][e] = 0.f;

    const int q  = lane & 3;
    const int r4 = lane >> 2;
    const int g  = lane >> 3;
    const int l7 = lane & 7;
    const uint32_t aoff  = (wm * 64 + l7 + ((g & 1) << 3)) * 144 + ((g >> 1) << 4);
    const uint32_t boff0 = (wn * 32 + ((g >> 1)) * 8 + l7) * 144 + ((g & 1) << 4);
    const uint32_t boff1 = boff0 + 16 * 144;

    #pragma unroll
    for (int kc = 0; kc < 4; kc++) {
        const uint32_t kb = kc * 32;
        uint32_t bh[4][2], r[4];
        ldsm4(r, sbase + EPL + boff0 + kb);
        bh[0][0] = r[0]; bh[0][1] = r[1]; bh[1][0] = r[2]; bh[1][1] = r[3];
        ldsm4(r, sbase + EPL + boff1 + kb);
        bh[2][0] = r[0]; bh[2][1] = r[1]; bh[3][0] = r[2]; bh[3][1] = r[3];
        #pragma unroll
        for (int mt = 0; mt < 4; mt++) {
            uint32_t ah[4];
            ldsm4(ah, sbase + aoff + mt * 2304 + kb);
            #pragma unroll
            for (int nt = 0; nt < 4; nt++)
                mma_f16(acc[mt][nt], ah[0], ah[1], ah[2], ah[3], bh[nt][0], bh[nt][1]);
        }
    }

    // epilogue: exp, fp16 store, accumulate D over j
    float psum[4][2];
    #pragma unroll
    for (int nt = 0; nt < 4; nt++) { psum[nt][0] = 0.f; psum[nt][1] = 0.f; }

    #pragma unroll
    for (int mt = 0; mt < 4; mt++) {
        int jrow = j0 + wm * 64 + mt * 16 + r4;
        long r0 = ((long)b * N_ + jrow) * N_;
        long r8 = r0 + 8L * N_;
        #pragma unroll
        for (int nt = 0; nt < 4; nt++) {
            int col = i0 + wn * 32 + nt * 8 + 2 * q;
            float e0 = __expf(acc[mt][nt][0]);
            float e1 = __expf(acc[mt][nt][1]);
            float e2 = __expf(acc[mt][nt][2]);
            float e3 = __expf(acc[mt][nt][3]);
            uint32_t p01, p23;
            asm("cvt.rn.f16x2.f32 %0, %1, %2;" : "=r"(p01) : "f"(e1), "f"(e0));
            asm("cvt.rn.f16x2.f32 %0, %1, %2;" : "=r"(p23) : "f"(e3), "f"(e2));
            *(uint32_t*)&g_Ef[r0 + col] = p01;
            *(uint32_t*)&g_Ef[r8 + col] = p23;
            psum[nt][0] += e0 + e2;
            psum[nt][1] += e1 + e3;
        }
    }

    #pragma unroll
    for (int nt = 0; nt < 4; nt++)
        #pragma unroll
        for (int w = 0; w < 2; w++) {
            float v = psum[nt][w];
            v += __shfl_xor_sync(0xffffffffu, v, 4);
            v += __shfl_xor_sync(0xffffffffu, v, 8);
            v += __shfl_xor_sync(0xffffffffu, v, 16);
            if (lane < 4)
                atomicAdd(&sD[wn * 32 + nt * 8 + 2 * lane + w], v);
        }
    __syncthreads();
    if (tid < 128) atomicAdd(&g_D[b * N_ + i0 + tid], sD[tid]);
}

// ---------------- vout: out = (Af . Ef^T)/ASCALE + gb   (1-term f16, k-stage 64) ---
// 128x128 CTA tile, depth-3 cp.async pipeline, smem row stride 144B (2 planes).
#define VPL 18432                 // 128 rows * 144B
#define VSTG (2 * VPL)            // 36864
#define SMEM_V (3 * VSTG)         // 110592 -> 2 CTAs/SM (221KB <= 228KB carveout)

__global__ void __launch_bounds__(256, 2)
vout_kernel(float* __restrict__ out, const float* __restrict__ gb, float oscale)
{
    extern __shared__ char smem[];
    const uint32_t sbase = smem_u32(smem);
    const int tid = threadIdx.x;
    const int lane = tid & 31;
    const int wid  = tid >> 5;
    const int wm = wid >> 2;            // 0..1
    const int wn = wid & 3;             // 0..3
    const int b  = blockIdx.z;
    const int m0 = blockIdx.y * 128;    // c tile
    const int n0 = blockIdx.x * 128;    // j tile

    // hoisted cp.async addressing: per plane 1024 16B-chunks over 256 threads
    const int rr = tid >> 3;            // 0..31 (+u*32)
    const int c8 = tid & 7;
    const u16* pA = g_Af + ((long)b * C_ + m0 + rr) * N_ + c8 * 8;
    const u16* pB = g_Ef + ((long)b * N_ + n0 + rr) * N_ + c8 * 8;
    const uint32_t dD = (uint32_t)(rr * 144 + c8 * 16);

    auto issue = [&](int t, int s) {
        const int kt = t * 64;
        const uint32_t d0 = sbase + s * VSTG + dD;
        #pragma unroll
        for (int u = 0; u < 4; u++) {
            cp16(d0 + u * 32 * 144,       pA + (long)u * 32 * N_ + kt);
            cp16(d0 + VPL + u * 32 * 144, pB + (long)u * 32 * N_ + kt);
        }
        CP_COMMIT();
    };

    float acc[4][4][4];
    #pragma unroll
    for (int mt = 0; mt < 4; mt++)
        #pragma unroll
        for (int nt = 0; nt < 4; nt++)
            #pragma unroll
            for (int e = 0; e < 4; e++) acc[mt][nt][e] = 0.f;

    const int q  = lane & 3;
    const int r4 = lane >> 2;
    const int g  = lane >> 3;
    const int l7 = lane & 7;
    const uint32_t aoff  = (wm * 64 + l7 + ((g & 1) << 3)) * 144 + ((g >> 1) << 4);
    const uint32_t boff0 = (wn * 32 + ((g >> 1)) * 8 + l7) * 144 + ((g & 1) << 4);
    const uint32_t boff1 = boff0 + 16 * 144;

    auto compute = [&](int s) {
        const uint32_t buf = sbase + s * VSTG;
        #pragma unroll
        for (int kc = 0; kc < 4; kc++) {
            const uint32_t kb = kc * 32;
            uint32_t bh[4][2], r[4];
            ldsm4(r, buf + VPL + boff0 + kb);
            bh[0][0] = r[0]; bh[0][1] = r[1]; bh[1][0] = r[2]; bh[1][1] = r[3];
            ldsm4(r, buf + VPL + boff1 + kb);
            bh[2][0] = r[0]; bh[2][1] = r[1]; bh[3][0] = r[2]; bh[3][1] = r[3];
            #pragma unroll
            for (int mt = 0; mt < 4; mt++) {
                uint32_t ah[4];
                ldsm4(ah, buf + aoff + mt * 2304 + kb);
                #pragma unroll
                for (int nt = 0; nt < 4; nt++)
                    mma_f16(acc[mt][nt], ah[0], ah[1], ah[2], ah[3], bh[nt][0], bh[nt][1]);
            }
        }
    };

    const int kstages = N_ / 64;        // 36
    issue(0, 0);
    issue(1, 1);
    for (int t = 0; t < kstages; t++) {
        CP_WAIT(1);
        __syncthreads();
        if (t + 2 < kstages) issue(t + 2, (t + 2) % 3);
        else CP_COMMIT();
        compute(t % 3);
    }

    // epilogue: fp32 out * oscale + per-c bias
    #pragma unroll
    for (int mt = 0; mt < 4; mt++) {
        int rA = m0 + wm * 64 + mt * 16 + r4;
        float bv0 = gb[rA];
        float bv8 = gb[rA + 8];
        long r0 = ((long)b * C_ + rA) * N_;
        long r8 = r0 + 8L * N_;
        #pragma unroll
        for (int nt = 0; nt < 4; nt++) {
            int col = n0 + wn * 32 + nt * 8 + q * 2;
            float2 v0, v1;
            v0.x = acc[mt][nt][0] * oscale + bv0;
            v0.y = acc[mt][nt][1] * oscale + bv0;
            v1.x = acc[mt][nt][2] * oscale + bv8;
            v1.y = acc[mt][nt][3] * oscale + bv8;
            *(float2*)&out[r0 + col] = v0;
            *(float2*)&out[r8 + col] = v1;
        }
    }
}

// ---------------- launch ----------------------------------------------------------
extern "C" void kernel_launch(void* const* d_in, const int* in_sizes, int n_in,
                              void* d_out, int out_size)
{
    const float* x  = (const float*)d_in[0];
    const float* qw = (const float*)d_in[1];
    const float* qb = (const float*)d_in[2];
    const float* kw = (const float*)d_in[3];
    const float* kb = (const float*)d_in[4];
    const float* vw = (const float*)d_in[5];
    const float* vb = (const float*)d_in[6];
    const float* gw = (const float*)d_in[7];
    const float* gb = (const float*)d_in[8];
    float* out = (float*)d_out;

    void *pxh, *pxl, *pqkh, *pqkl, *pgvh, *pgvl, *pbias,
         *pQf, *pAf, *pD;
    cudaGetSymbolAddress(&pxh,  g_xthi);
    cudaGetSymbolAddress(&pxl,  g_xtlo);
    cudaGetSymbolAddress(&pqkh, g_Wqkhi);
    cudaGetSymbolAddress(&pqkl, g_Wqklo);
    cudaGetSymbolAddress(&pgvh, g_Wgvhi);
    cudaGetSymbolAddress(&pgvl, g_Wgvlo);
    cudaGetSymbolAddress(&pbias, g_biasA);
    cudaGetSymbolAddress(&pQf,  g_QKtf);
    cudaGetSymbolAddress(&pAf,  g_Af);
    cudaGetSymbolAddress(&pD,   g_D);

    auto kQK  = gemm3_kernel<2, true,  true,  false, 3>;
    auto kGV  = gemm3_kernel<2, true,  true,  false, 4>;
    const int SMEM_QK  = 2 * 4 * 128 * 80;   // 81920

    cudaFuncSetAttribute(kQK,  cudaFuncAttributeMaxDynamicSharedMemorySize, SMEM_QK);
    cudaFuncSetAttribute(kGV,  cudaFuncAttributeMaxDynamicSharedMemorySize, SMEM_QK);
    cudaFuncSetAttribute(vout_kernel,
                         cudaFuncAttributeMaxDynamicSharedMemorySize, SMEM_V);
    cudaFuncSetAttribute(energy_mma_kernel,
                         cudaFuncAttributeMaxDynamicSharedMemorySize, SMEM_E);

    // K0: weight planes (gamma folded into value) + zero D
    build_w_kernel<<<384, 256>>>(qw, qb, kw, kb, vw, vb, gw);

    // x -> transposed bf16 planes
    xsplit_kernel<<<dim3(N_ / 64, C_ / 64, B_), 256>>>(x);

    // QKtf[b][i][ck] = xt . Wqk^T + bias  (single f16 out, per-n bias)
    kQK<<<dim3(1, N_ / 128, B_), 256, SMEM_QK>>>(
        C_ / 32,
        (const u16*)pxh, (const u16*)pxl, N_, C_,
        (const u16*)pqkh, (const u16*)pqkl, 0, C_,
        nullptr, (u16*)pQf, nullptr, N_, 128, (const float*)pbias,
        nullptr, 1.f);

    // E plane (fp16) + D sums  (1-term f16 MMA)
    energy_mma_kernel<<<dim3(N_ / 128, N_ / 128, B_), 256, SMEM_E>>>();

    // A plane = f16((Wgv . xt^T + bias) * ASCALE / D)  (fused prescale, 1 plane)
    kGV<<<dim3(N_ / 128, C_ / 128, B_), 256, SMEM_QK>>>(
        C_ / 32,
        (const u16*)pgvh, (const u16*)pgvl, 0, C_,
        (const u16*)pxh, (const u16*)pxl, N_, C_,
        nullptr, (u16*)pAf, nullptr, C_, N_, (const float*)pbias + 128,
        (const float*)pD, 1.f);

    // out[b][c][j] = (Af . Ef^T) / 4096 + gb  (1-term f16, k-stage 64, depth-3)
    vout_kernel<<<dim3(N_ / 128, C_ / 128, B_), 256, SMEM_V>>>(
        out, gb, 1.f / ASCALE);
}